// round 14
// baseline (speedup 1.0000x reference)
#include <cuda_runtime.h>
#include <cuda_fp16.h>
#include <cstdint>

#define B 2
#define C 192
#define C3 576
#define SDIM 32
#define NPTS 32768           // 32^3
#define HEADS 4
#define CH 48
#define EPS 1e-12f

// ---------------- scratch (static device allocations) ----------------
__device__ __half g_xh  [(size_t)B * C * NPTS];      // input x in fp16
__device__ __half g_qkvh[(size_t)B * C3 * NPTS];     // after 1x1 conv (fp16)
__device__ __half g_dwh [(size_t)B * C3 * NPTS];     // after dwconv: q,k,v fp16
__device__ float  g_ssq[B * 2 * C];                  // sum of squares of ROUNDED q/k
__device__ float  g_at [B * HEADS * CH * CH];        // attention logits / probs
__device__ __half g_wh [C3 * C];                     // qkv weights fp16
__device__ __half g_w2h[B * C * C];                  // fused proj∘attn weights fp16

// ================= mma.sync helpers =================
__device__ __forceinline__ uint32_t smem_u32(const void* p) {
    uint32_t a;
    asm("{ .reg .u64 t; cvta.to.shared.u64 t, %1; cvt.u32.u64 %0, t; }" : "=r"(a) : "l"(p));
    return a;
}
__device__ __forceinline__ void ldsm4(uint32_t* r, uint32_t a) {
    asm volatile("ldmatrix.sync.aligned.m8n8.x4.shared.b16 {%0,%1,%2,%3}, [%4];"
                 : "=r"(r[0]), "=r"(r[1]), "=r"(r[2]), "=r"(r[3]) : "r"(a));
}
__device__ __forceinline__ void ldsm4t(uint32_t* r, uint32_t a) {
    asm volatile("ldmatrix.sync.aligned.m8n8.x4.trans.shared.b16 {%0,%1,%2,%3}, [%4];"
                 : "=r"(r[0]), "=r"(r[1]), "=r"(r[2]), "=r"(r[3]) : "r"(a));
}
__device__ __forceinline__ void mma_f16(float* d, const uint32_t* a, const uint32_t* b) {
    asm volatile(
        "mma.sync.aligned.m16n8k16.row.col.f32.f16.f16.f32 "
        "{%0,%1,%2,%3}, {%4,%5,%6,%7}, {%8,%9}, {%0,%1,%2,%3};"
        : "+f"(d[0]), "+f"(d[1]), "+f"(d[2]), "+f"(d[3])
        : "r"(a[0]), "r"(a[1]), "r"(a[2]), "r"(a[3]), "r"(b[0]), "r"(b[1]));
}
#define CP_CG16(dst, src) \
    asm volatile("cp.async.cg.shared.global [%0], [%1], 16;" :: "r"(dst), "l"(src))
#define CP_COMMIT() asm volatile("cp.async.commit_group;")

// ================= packed fp32x2 helpers (sm_100+ family) =================
typedef unsigned long long u64t;
__device__ __forceinline__ u64t pk2(float lo, float hi) {
    u64t d;
    asm("mov.b64 %0, {%1, %2};" : "=l"(d) : "f"(lo), "f"(hi));
    return d;
}
__device__ __forceinline__ void upk2(u64t d, float& lo, float& hi) {
    asm("mov.b64 {%0, %1}, %2;" : "=f"(lo), "=f"(hi) : "l"(d));
}
__device__ __forceinline__ void fma2(u64t& a, u64t x, u64t y) {
    asm("fma.rn.f32x2 %0, %1, %2, %0;" : "+l"(a) : "l"(x), "l"(y));
}
__device__ __forceinline__ u64t add2(u64t x, u64t y) {
    u64t d;
    asm("add.rn.f32x2 %0, %1, %2;" : "=l"(d) : "l"(x), "l"(y));
    return d;
}

// ---------------- unified setup: x->fp16, W->fp16, zero attn ----------------
#define XG ((size_t)B * C * NPTS / 4)              // float4 groups in x
__global__ void setupk(const float* __restrict__ x, __half* __restrict__ xh,
                       const float* __restrict__ qkv_w, __half* __restrict__ wh,
                       float* __restrict__ attn)
{
    size_t i = (size_t)blockIdx.x * 256 + threadIdx.x;
    if (i < XG) {
        size_t j = i * 4;
        float4 v = *reinterpret_cast<const float4*>(&x[j]);
        __half2 h0 = __floats2half2_rn(v.x, v.y);
        __half2 h1 = __floats2half2_rn(v.z, v.w);
        uint2 r = {*reinterpret_cast<uint32_t*>(&h0), *reinterpret_cast<uint32_t*>(&h1)};
        *reinterpret_cast<uint2*>(&xh[j]) = r;
    } else if (i < XG + (size_t)C3 * C) {
        int j = (int)(i - XG);
        wh[j] = __float2half_rn(qkv_w[j]);
    } else if (i < XG + (size_t)C3 * C + B * HEADS * CH * CH) {
        attn[i - XG - (size_t)C3 * C] = 0.f;
    }
}

// ---------------- 1x1 conv GEMM via fp16 mma.sync, 3-stage cp.async.cg ------------
#define BMg 96
#define BNg 128
#define BKg 32
#define PA 40
#define PB 136
#define SA_BYTES (BMg * PA * 2)      // 7680
#define SB_BYTES (BKg * PB * 2)      // 8704
#define GM_SMEM  (3 * (SA_BYTES + SB_BYTES))   // 49152
#define NIT (C / BKg)                // 6

template<int OHALF>
__global__ __launch_bounds__(256, 2) void gemm_mma(
    const __half* __restrict__ Xall, size_t xbs,
    const __half* __restrict__ WH, size_t wbs,
    const float* __restrict__ bias, void* __restrict__ Yall, size_t ybs)
{
    extern __shared__ char gsm[];
    const int tid = threadIdx.x, wid = tid >> 5, lane = tid & 31;
    const int o0 = blockIdx.x * BMg;
    const int n0 = blockIdx.y * BNg;
    const __half* X = Xall + (size_t)blockIdx.z * xbs;
    const __half* W = WH + (size_t)blockIdx.z * wbs;

    const int warp_m = (wid >> 2) * 48;
    const int warp_n = (wid & 3) * 32;

    const uint32_t bA = smem_u32(gsm);
    const uint32_t bB = bA + 3 * SA_BYTES;
    const uint32_t aOff = ((warp_m + (lane & 15)) * PA + (lane >> 4) * 8) * 2;

    const int ar0 = tid >> 2,        ac0 = (tid & 3) * 8;
    const int ar1 = 64 + (tid >> 2), ac1 = (tid & 3) * 8;
    const int br0 = tid >> 4,        bc0 = (tid & 15) * 8;
    const int br1 = 16 + (tid >> 4), bc1 = (tid & 15) * 8;

    auto prefetch = [&](int it) {
        const int kc = it * BKg;
        const int s  = it % 3;
        const uint32_t dA = bA + s * SA_BYTES;
        const uint32_t dB = bB + s * SB_BYTES;
        CP_CG16(dA + (ar0 * PA + ac0) * 2, &W[(size_t)(o0 + ar0) * C + kc + ac0]);
        if (tid < 128)
            CP_CG16(dA + (ar1 * PA + ac1) * 2, &W[(size_t)(o0 + ar1) * C + kc + ac1]);
        CP_CG16(dB + (br0 * PB + bc0) * 2, &X[(size_t)(kc + br0) * NPTS + n0 + bc0]);
        CP_CG16(dB + (br1 * PB + bc1) * 2, &X[(size_t)(kc + br1) * NPTS + n0 + bc1]);
        CP_COMMIT();
    };

    prefetch(0);
    prefetch(1);

    float acc[3][4][4] = {};

    #pragma unroll
    for (int it = 0; it < NIT; it++) {
        if (it < NIT - 1) asm volatile("cp.async.wait_group 1;");
        else              asm volatile("cp.async.wait_group 0;");
        __syncthreads();
        if (it + 2 < NIT) prefetch(it + 2);

        const int s = it % 3;
        const uint32_t stA = bA + s * SA_BYTES;
        const uint32_t stB = bB + s * SB_BYTES;
        #pragma unroll
        for (int ks = 0; ks < 2; ks++) {
            uint32_t Bf[4][2];
            #pragma unroll
            for (int jj = 0; jj < 2; jj++) {
                uint32_t r[4];
                uint32_t off = (((lane & 15) + ks * 16) * PB +
                                warp_n + jj * 16 + (lane >> 4) * 8) * 2;
                ldsm4t(r, stB + off);
                Bf[2 * jj][0] = r[0]; Bf[2 * jj][1] = r[1];
                Bf[2 * jj + 1][0] = r[2]; Bf[2 * jj + 1][1] = r[3];
            }
            #pragma unroll
            for (int i = 0; i < 3; i++) {
                uint32_t Af[4];
                ldsm4(Af, stA + aOff + i * (16 * PA * 2) + ks * 32);
                #pragma unroll
                for (int j = 0; j < 4; j++)
                    mma_f16(acc[i][j], Af, Bf[j]);
            }
        }
    }

    #pragma unroll
    for (int i = 0; i < 3; i++) {
        int m = o0 + warp_m + i * 16 + (lane >> 2);
        float bv0 = bias[m], bv1 = bias[m + 8];
        #pragma unroll
        for (int j = 0; j < 4; j++) {
            int n = n0 + warp_n + j * 8 + (lane & 3) * 2;
            if (OHALF) {
                __half* Y = (__half*)Yall + (size_t)blockIdx.z * ybs;
                __half2 r0 = __floats2half2_rn(acc[i][j][0] + bv0, acc[i][j][1] + bv0);
                __half2 r1 = __floats2half2_rn(acc[i][j][2] + bv1, acc[i][j][3] + bv1);
                *reinterpret_cast<__half2*>(&Y[(size_t)m * NPTS + n]) = r0;
                *reinterpret_cast<__half2*>(&Y[(size_t)(m + 8) * NPTS + n]) = r1;
            } else {
                float* Y = (float*)Yall + (size_t)blockIdx.z * ybs;
                float2 r0 = {acc[i][j][0] + bv0, acc[i][j][1] + bv0};
                float2 r1 = {acc[i][j][2] + bv1, acc[i][j][3] + bv1};
                *reinterpret_cast<float2*>(&Y[(size_t)m * NPTS + n]) = r0;
                *reinterpret_cast<float2*>(&Y[(size_t)(m + 8) * NPTS + n]) = r1;
            }
        }
    }
}

// ---------------- depthwise 3x3x3: z-rotation + packed fp32x2 FMA ------------------
__global__ __launch_bounds__(256) void dwconv3(
    const __half* __restrict__ in, const float* __restrict__ w,
    const float* __restrict__ bias, __half* __restrict__ outh,
    float* __restrict__ ssq)
{
    int bc = blockIdx.x;
    int b  = bc / C3;
    int c  = bc % C3;
    const __half* vol = in + (size_t)bc * NPTS;
    __half* op = outh + (size_t)bc * NPTS;

    u64t ww[27];
    #pragma unroll
    for (int i = 0; i < 27; i++) { float wv = w[c * 27 + i]; ww[i] = pk2(wv, wv); }
    float bv = bias[c];
    const u64t bb = pk2(bv, bv);

    __shared__ float P[2][34][36];
    __shared__ float sred[8];
    int tid = threadIdx.x;
    for (int i = tid; i < 2 * 34 * 36; i += 256) ((float*)P)[i] = 0.f;
    __syncthreads();

    const int ly = tid >> 3, lx4 = (tid & 7) * 4;
    {
        uint2 raw = *reinterpret_cast<const uint2*>(&vol[ly * 32 + lx4]);
        __half2 hA = *reinterpret_cast<__half2*>(&raw.x);
        __half2 hB = *reinterpret_cast<__half2*>(&raw.y);
        P[0][1 + ly][1 + lx4 + 0] = __half2float(hA.x);
        P[0][1 + ly][1 + lx4 + 1] = __half2float(hA.y);
        P[0][1 + ly][1 + lx4 + 2] = __half2float(hB.x);
        P[0][1 + ly][1 + lx4 + 3] = __half2float(hB.y);
    }
    __syncthreads();

    float qs = 0.f;
    const bool is_qk = (c < 2 * C);

    u64t a0L = bb, a0H = bb, a1L = bb, a1H = bb;

    for (int z = 0; z < SDIM; z++) {
        uint2 raw;
        if (z + 1 < SDIM)
            raw = *reinterpret_cast<const uint2*>(&vol[(size_t)(z + 1) * 1024 + ly * 32 + lx4]);

        u64t cdL[3] = {0, 0, 0}, cdH[3] = {0, 0, 0};
        const int s = z & 1;
        #pragma unroll
        for (int dy = 0; dy < 3; dy++) {
            const float* row = &P[s][ly + dy][lx4];
            float4 rA = *reinterpret_cast<const float4*>(row);
            float2 rB = *reinterpret_cast<const float2*>(row + 4);
            u64t p0 = pk2(rA.x, rA.y), p1 = pk2(rA.y, rA.z), p2 = pk2(rA.z, rA.w);
            u64t p3 = pk2(rA.w, rB.x), p4 = pk2(rB.x, rB.y);
            #pragma unroll
            for (int dz = 0; dz < 3; dz++) {
                const int base = dz * 9 + dy * 3;
                fma2(cdL[dz], ww[base + 0], p0);
                fma2(cdL[dz], ww[base + 1], p1);
                fma2(cdL[dz], ww[base + 2], p2);
                fma2(cdH[dz], ww[base + 0], p2);
                fma2(cdH[dz], ww[base + 1], p3);
                fma2(cdH[dz], ww[base + 2], p4);
            }
        }

        if (z > 0) {
            u64t oL = add2(a0L, cdL[2]);
            u64t oH = add2(a0H, cdH[2]);
            float o0, o1, o2, o3;
            upk2(oL, o0, o1); upk2(oH, o2, o3);
            __half2 h0 = __floats2half2_rn(o0, o1);
            __half2 h1 = __floats2half2_rn(o2, o3);
            uint2 hv = {*reinterpret_cast<uint32_t*>(&h0), *reinterpret_cast<uint32_t*>(&h1)};
            *reinterpret_cast<uint2*>(&op[(size_t)(z - 1) * 1024 + ly * 32 + lx4]) = hv;
            if (is_qk) {
                float r0 = __half2float(h0.x), r1 = __half2float(h0.y);
                float r2 = __half2float(h1.x), r3 = __half2float(h1.y);
                qs += r0 * r0 + r1 * r1 + r2 * r2 + r3 * r3;
            }
        }
        a0L = add2(a1L, cdL[1]); a0H = add2(a1H, cdH[1]);
        a1L = add2(bb, cdL[0]);  a1H = add2(bb, cdH[0]);

        if (z + 1 < SDIM) {
            __half2 hA = *reinterpret_cast<__half2*>(&raw.x);
            __half2 hB = *reinterpret_cast<__half2*>(&raw.y);
            P[s ^ 1][1 + ly][1 + lx4 + 0] = __half2float(hA.x);
            P[s ^ 1][1 + ly][1 + lx4 + 1] = __half2float(hA.y);
            P[s ^ 1][1 + ly][1 + lx4 + 2] = __half2float(hB.x);
            P[s ^ 1][1 + ly][1 + lx4 + 3] = __half2float(hB.y);
        }
        __syncthreads();
    }
    {
        float o0, o1, o2, o3;
        upk2(a0L, o0, o1); upk2(a0H, o2, o3);
        __half2 h0 = __floats2half2_rn(o0, o1);
        __half2 h1 = __floats2half2_rn(o2, o3);
        uint2 hv = {*reinterpret_cast<uint32_t*>(&h0), *reinterpret_cast<uint32_t*>(&h1)};
        *reinterpret_cast<uint2*>(&op[(size_t)31 * 1024 + ly * 32 + lx4]) = hv;
        if (is_qk) {
            float r0 = __half2float(h0.x), r1 = __half2float(h0.y);
            float r2 = __half2float(h1.x), r3 = __half2float(h1.y);
            qs += r0 * r0 + r1 * r1 + r2 * r2 + r3 * r3;
        }
    }

    if (is_qk) {
        #pragma unroll
        for (int o = 16; o > 0; o >>= 1) qs += __shfl_xor_sync(~0u, qs, o);
        if ((tid & 31) == 0) sred[tid >> 5] = qs;
        __syncthreads();
        if (tid < 8) {
            float v = sred[tid];
            #pragma unroll
            for (int o = 4; o > 0; o >>= 1) v += __shfl_xor_sync(0xffu, v, o);
            if (tid == 0) ssq[b * 2 * C + c] = v;
        }
    }
}

// ---------------- q @ k^T via fp16 mma.sync ----------------
#define QKC 128
#define QKP 136
#define QK_ARR (48 * QKP * 2)
#define QK_STAGE (2 * QK_ARR)
#define QK_NSPL 64
#define QK_SLAB (NPTS / QK_NSPL)     // 512
#define QK_SMEM (2 * QK_STAGE + 48 * 49 * 4)

__global__ __launch_bounds__(256) void qk_mma(
    const __half* __restrict__ dwh, float* __restrict__ attn)
{
    extern __shared__ char smem[];
    float* sAcc = reinterpret_cast<float*>(smem + 2 * QK_STAGE);
    const int tid = threadIdx.x, wid = tid >> 5, lane = tid & 31;
    const int b = blockIdx.z, h = blockIdx.y;
    const int n0 = blockIdx.x * QK_SLAB;

    const __half* srcs[2] = {
        dwh + ((size_t)b * C3 + h * CH) * NPTS,
        dwh + ((size_t)b * C3 + C + h * CH) * NPTS
    };
    const uint32_t sbase = smem_u32(smem);

    for (int i = tid; i < 48 * 49; i += 256) sAcc[i] = 0.f;

    int la[6], lr[6], lc[6];
    #pragma unroll
    for (int q = 0; q < 6; q++) {
        int idx = tid + q * 256;
        la[q] = idx / 768;
        int rem = idx % 768;
        lr[q] = rem / 16;
        lc[q] = (rem % 16) * 8;
    }

    const int NCH = QK_SLAB / QKC;   // 4
    #pragma unroll
    for (int q = 0; q < 6; q++) {
        uint32_t dst = sbase + la[q] * QK_ARR + (lr[q] * QKP + lc[q]) * 2;
        CP_CG16(dst, srcs[la[q]] + (size_t)lr[q] * NPTS + n0 + lc[q]);
    }
    CP_COMMIT();

    float acc[3][6][4] = {};
    const int k0 = wid * 16;

    for (int ch = 0; ch < NCH; ch++) {
        if (ch + 1 < NCH) {
            uint32_t st = ((ch + 1) & 1) * QK_STAGE;
            int nb = n0 + (ch + 1) * QKC;
            #pragma unroll
            for (int q = 0; q < 6; q++) {
                uint32_t dst = sbase + st + la[q] * QK_ARR + (lr[q] * QKP + lc[q]) * 2;
                CP_CG16(dst, srcs[la[q]] + (size_t)lr[q] * NPTS + nb + lc[q]);
            }
            CP_COMMIT();
            asm volatile("cp.async.wait_group 1;");
        } else {
            asm volatile("cp.async.wait_group 0;");
        }
        __syncthreads();

        const uint32_t st = sbase + (ch & 1) * QK_STAGE;
        uint32_t Af[3][4], Bf[6][2];
        #pragma unroll
        for (int i = 0; i < 3; i++) {
            uint32_t off = ((i * 16 + (lane & 15)) * QKP + k0 + (lane >> 4) * 8) * 2;
            ldsm4(Af[i], st + off);
        }
        #pragma unroll
        for (int jj = 0; jj < 3; jj++) {
            uint32_t r[4];
            uint32_t off = ((jj * 16 + (lane & 7) + ((lane >> 4) << 3)) * QKP +
                            k0 + ((lane >> 3) & 1) * 8) * 2;
            ldsm4(r, st + QK_ARR + off);
            Bf[2 * jj][0] = r[0]; Bf[2 * jj][1] = r[1];
            Bf[2 * jj + 1][0] = r[2]; Bf[2 * jj + 1][1] = r[3];
        }
        #pragma unroll
        for (int i = 0; i < 3; i++)
            #pragma unroll
            for (int j = 0; j < 6; j++)
                mma_f16(acc[i][j], Af[i], Bf[j]);
        __syncthreads();
    }

    #pragma unroll
    for (int i = 0; i < 3; i++) {
        int m = i * 16 + (lane >> 2);
        #pragma unroll
        for (int j = 0; j < 6; j++) {
            int n = j * 8 + (lane & 3) * 2;
            atomicAdd(&sAcc[m * 49 + n],           acc[i][j][0]);
            atomicAdd(&sAcc[m * 49 + n + 1],       acc[i][j][1]);
            atomicAdd(&sAcc[(m + 8) * 49 + n],     acc[i][j][2]);
            atomicAdd(&sAcc[(m + 8) * 49 + n + 1], acc[i][j][3]);
        }
    }
    __syncthreads();
    float* dst = attn + (size_t)(b * HEADS + h) * CH * CH;
    for (int i = tid; i < CH * CH; i += 256)
        atomicAdd(&dst[i], sAcc[(i / CH) * 49 + (i % CH)]);
}

// ---------------- fused softmax + proj∘attn weight build (8 blocks, 192 thr) -------
__global__ __launch_bounds__(192) void smfuse(
    const float* __restrict__ attn, const float* __restrict__ ssq,
    const float* __restrict__ temp, const float* __restrict__ proj_w,
    __half* __restrict__ w2)
{
    int bh = blockIdx.x;
    int h = bh % HEADS, b = bh / HEADS;
    __shared__ float At[CH][CH];           // post-softmax attn [c][e]
    const float* am = attn + (size_t)bh * CH * CH;
    const float t = temp[h];

    // phase 1: softmax; 4 threads per row, 12 e-values each
    {
        int c = threadIdx.x >> 2, qq = threadIdx.x & 3;
        float iq = 1.f / fmaxf(sqrtf(ssq[b * 2 * C + h * CH + c]), EPS);
        float xv[12];
        float mx = -1e30f;
        #pragma unroll
        for (int u = 0; u < 12; u++) {
            int e = qq * 12 + u;
            float ik = 1.f / fmaxf(sqrtf(ssq[b * 2 * C + C + h * CH + e]), EPS);
            xv[u] = am[c * CH + e] * iq * ik * t;
            mx = fmaxf(mx, xv[u]);
        }
        mx = fmaxf(mx, __shfl_xor_sync(~0u, mx, 1));
        mx = fmaxf(mx, __shfl_xor_sync(~0u, mx, 2));
        float sm = 0.f;
        #pragma unroll
        for (int u = 0; u < 12; u++) { xv[u] = expf(xv[u] - mx); sm += xv[u]; }
        sm += __shfl_xor_sync(~0u, sm, 1);
        sm += __shfl_xor_sync(~0u, sm, 2);
        float r = 1.f / sm;
        #pragma unroll
        for (int u = 0; u < 12; u++) At[c][qq * 12 + u] = xv[u] * r;
    }
    __syncthreads();

    // phase 2: w2[b][o][h*48+e] = sum_c proj[o, h*48+c] * At[c][e]
    int o = threadIdx.x;
    float pr[CH];
    #pragma unroll
    for (int c = 0; c < CH; c++) pr[c] = proj_w[(size_t)o * C + h * CH + c];

    __half* dst = w2 + (size_t)b * C * C + (size_t)o * C + h * CH;
    #pragma unroll 4
    for (int e = 0; e < CH; e++) {
        float acc = 0.f;
        #pragma unroll
        for (int c = 0; c < CH; c++) acc += pr[c] * At[c][e];
        dst[e] = __float2half_rn(acc);
    }
}

// ---------------- launch ----------------
extern "C" void kernel_launch(void* const* d_in, const int* in_sizes, int n_in,
                              void* d_out, int out_size)
{
    const float* x      = (const float*)d_in[0];
    const float* qkv_w  = (const float*)d_in[1];
    const float* qkv_b  = (const float*)d_in[2];
    const float* dw_w   = (const float*)d_in[3];
    const float* dw_b   = (const float*)d_in[4];
    const float* proj_w = (const float*)d_in[5];
    const float* proj_b = (const float*)d_in[6];
    const float* temp   = (const float*)d_in[7];
    float* out = (float*)d_out;

    float *ssqp, *atp;
    __half *xhp, *qkvhp, *dwhp, *whp, *w2p;
    cudaGetSymbolAddress((void**)&xhp,   g_xh);
    cudaGetSymbolAddress((void**)&qkvhp, g_qkvh);
    cudaGetSymbolAddress((void**)&dwhp,  g_dwh);
    cudaGetSymbolAddress((void**)&ssqp,  g_ssq);
    cudaGetSymbolAddress((void**)&atp,   g_at);
    cudaGetSymbolAddress((void**)&whp,   g_wh);
    cudaGetSymbolAddress((void**)&w2p,   g_w2h);

    cudaFuncSetAttribute(qk_mma, cudaFuncAttributeMaxDynamicSharedMemorySize, QK_SMEM);
    cudaFuncSetAttribute(gemm_mma<1>, cudaFuncAttributeMaxDynamicSharedMemorySize, GM_SMEM);
    cudaFuncSetAttribute(gemm_mma<0>, cudaFuncAttributeMaxDynamicSharedMemorySize, GM_SMEM);

    const size_t SETUP_N = XG + (size_t)C3 * C + B * HEADS * CH * CH;
    // 1) unified setup (x->fp16, W->fp16, zero attn)
    setupk<<<(int)((SETUP_N + 255) / 256), 256>>>(x, xhp, qkv_w, whp, atp);
    // 2) qkv 1x1 conv
    gemm_mma<1><<<dim3(C3 / BMg, NPTS / BNg, B), 256, GM_SMEM>>>(
        xhp, (size_t)C * NPTS, whp, 0, qkv_b, qkvhp, (size_t)C3 * NPTS);
    // 3) depthwise 3x3x3
    dwconv3<<<B * C3, 256>>>(qkvhp, dw_w, dw_b, dwhp, ssqp);
    // 4) q @ k^T (NSPL=64) <- PROFILED
    qk_mma<<<dim3(QK_NSPL, HEADS, B), 256, QK_SMEM>>>(dwhp, atp);
    // 5) fused softmax + proj∘attn weights
    smfuse<<<B * HEADS, 192>>>(atp, ssqp, temp, proj_w, w2p);
    // 6) fused (proj∘attn) @ v
    gemm_mma<0><<<dim3(C / BMg, NPTS / BNg, B), 256, GM_SMEM>>>(
        dwhp + (size_t)2 * C * NPTS, (size_t)C3 * NPTS,
        w2p, (size_t)C * C, proj_b, out, (size_t)C * NPTS);
}

// round 15
// speedup vs baseline: 1.0456x; 1.0456x over previous
#include <cuda_runtime.h>
#include <cuda_fp16.h>
#include <cstdint>

#define B 2
#define C 192
#define C3 576
#define SDIM 32
#define NPTS 32768           // 32^3
#define HEADS 4
#define CH 48
#define EPS 1e-12f

// ---------------- scratch (static device allocations) ----------------
__device__ __half g_xh  [(size_t)B * C * NPTS];      // input x in fp16
__device__ __half g_qkvh[(size_t)B * C3 * NPTS];     // after 1x1 conv (fp16)
__device__ __half g_dwh [(size_t)B * C3 * NPTS];     // after dwconv: q,k,v fp16
__device__ float  g_ssq[B * 2 * C];                  // sum of squares of ROUNDED q/k
__device__ float  g_at [B * HEADS * CH * CH];        // attention logits / probs
__device__ __half g_wh [C3 * C];                     // qkv weights fp16
__device__ __half g_w2h[B * C * C];                  // fused proj∘attn weights fp16

// ================= mma.sync helpers =================
__device__ __forceinline__ uint32_t smem_u32(const void* p) {
    uint32_t a;
    asm("{ .reg .u64 t; cvta.to.shared.u64 t, %1; cvt.u32.u64 %0, t; }" : "=r"(a) : "l"(p));
    return a;
}
__device__ __forceinline__ void ldsm4(uint32_t* r, uint32_t a) {
    asm volatile("ldmatrix.sync.aligned.m8n8.x4.shared.b16 {%0,%1,%2,%3}, [%4];"
                 : "=r"(r[0]), "=r"(r[1]), "=r"(r[2]), "=r"(r[3]) : "r"(a));
}
__device__ __forceinline__ void ldsm4t(uint32_t* r, uint32_t a) {
    asm volatile("ldmatrix.sync.aligned.m8n8.x4.trans.shared.b16 {%0,%1,%2,%3}, [%4];"
                 : "=r"(r[0]), "=r"(r[1]), "=r"(r[2]), "=r"(r[3]) : "r"(a));
}
__device__ __forceinline__ void mma_f16(float* d, const uint32_t* a, const uint32_t* b) {
    asm volatile(
        "mma.sync.aligned.m16n8k16.row.col.f32.f16.f16.f32 "
        "{%0,%1,%2,%3}, {%4,%5,%6,%7}, {%8,%9}, {%0,%1,%2,%3};"
        : "+f"(d[0]), "+f"(d[1]), "+f"(d[2]), "+f"(d[3])
        : "r"(a[0]), "r"(a[1]), "r"(a[2]), "r"(a[3]), "r"(b[0]), "r"(b[1]));
}
#define CP_CG16(dst, src) \
    asm volatile("cp.async.cg.shared.global [%0], [%1], 16;" :: "r"(dst), "l"(src))
#define CP_COMMIT() asm volatile("cp.async.commit_group;")

// ================= packed fp32x2 helpers (sm_100+ family) =================
typedef unsigned long long u64t;
__device__ __forceinline__ u64t pk2(float lo, float hi) {
    u64t d;
    asm("mov.b64 %0, {%1, %2};" : "=l"(d) : "f"(lo), "f"(hi));
    return d;
}
__device__ __forceinline__ void upk2(u64t d, float& lo, float& hi) {
    asm("mov.b64 {%0, %1}, %2;" : "=f"(lo), "=f"(hi) : "l"(d));
}
__device__ __forceinline__ void fma2(u64t& a, u64t x, u64t y) {
    asm("fma.rn.f32x2 %0, %1, %2, %0;" : "+l"(a) : "l"(x), "l"(y));
}
__device__ __forceinline__ u64t add2(u64t x, u64t y) {
    u64t d;
    asm("add.rn.f32x2 %0, %1, %2;" : "=l"(d) : "l"(x), "l"(y));
    return d;
}

// ---------------- unified setup: x->fp16, W->fp16, zero attn ----------------
#define XG ((size_t)B * C * NPTS / 4)              // float4 groups in x
__global__ void setupk(const float* __restrict__ x, __half* __restrict__ xh,
                       const float* __restrict__ qkv_w, __half* __restrict__ wh,
                       float* __restrict__ attn)
{
    size_t i = (size_t)blockIdx.x * 256 + threadIdx.x;
    if (i < XG) {
        size_t j = i * 4;
        float4 v = *reinterpret_cast<const float4*>(&x[j]);
        __half2 h0 = __floats2half2_rn(v.x, v.y);
        __half2 h1 = __floats2half2_rn(v.z, v.w);
        uint2 r = {*reinterpret_cast<uint32_t*>(&h0), *reinterpret_cast<uint32_t*>(&h1)};
        *reinterpret_cast<uint2*>(&xh[j]) = r;
    } else if (i < XG + (size_t)C3 * C) {
        int j = (int)(i - XG);
        wh[j] = __float2half_rn(qkv_w[j]);
    } else if (i < XG + (size_t)C3 * C + B * HEADS * CH * CH) {
        attn[i - XG - (size_t)C3 * C] = 0.f;
    }
}

// ---------------- 1x1 conv GEMM via fp16 mma.sync, 3-stage cp.async.cg ------------
#define BMg 96
#define BNg 128
#define BKg 32
#define PA 40
#define PB 136
#define SA_BYTES (BMg * PA * 2)      // 7680
#define SB_BYTES (BKg * PB * 2)      // 8704
#define GM_SMEM  (3 * (SA_BYTES + SB_BYTES))   // 49152
#define NIT (C / BKg)                // 6

template<int OHALF>
__global__ __launch_bounds__(256, 2) void gemm_mma(
    const __half* __restrict__ Xall, size_t xbs,
    const __half* __restrict__ WH, size_t wbs,
    const float* __restrict__ bias, void* __restrict__ Yall, size_t ybs)
{
    extern __shared__ char gsm[];
    const int tid = threadIdx.x, wid = tid >> 5, lane = tid & 31;
    const int o0 = blockIdx.x * BMg;
    const int n0 = blockIdx.y * BNg;
    const __half* X = Xall + (size_t)blockIdx.z * xbs;
    const __half* W = WH + (size_t)blockIdx.z * wbs;

    const int warp_m = (wid >> 2) * 48;
    const int warp_n = (wid & 3) * 32;

    const uint32_t bA = smem_u32(gsm);
    const uint32_t bB = bA + 3 * SA_BYTES;
    const uint32_t aOff = ((warp_m + (lane & 15)) * PA + (lane >> 4) * 8) * 2;

    const int ar0 = tid >> 2,        ac0 = (tid & 3) * 8;
    const int ar1 = 64 + (tid >> 2), ac1 = (tid & 3) * 8;
    const int br0 = tid >> 4,        bc0 = (tid & 15) * 8;
    const int br1 = 16 + (tid >> 4), bc1 = (tid & 15) * 8;

    auto prefetch = [&](int it) {
        const int kc = it * BKg;
        const int s  = it % 3;
        const uint32_t dA = bA + s * SA_BYTES;
        const uint32_t dB = bB + s * SB_BYTES;
        CP_CG16(dA + (ar0 * PA + ac0) * 2, &W[(size_t)(o0 + ar0) * C + kc + ac0]);
        if (tid < 128)
            CP_CG16(dA + (ar1 * PA + ac1) * 2, &W[(size_t)(o0 + ar1) * C + kc + ac1]);
        CP_CG16(dB + (br0 * PB + bc0) * 2, &X[(size_t)(kc + br0) * NPTS + n0 + bc0]);
        CP_CG16(dB + (br1 * PB + bc1) * 2, &X[(size_t)(kc + br1) * NPTS + n0 + bc1]);
        CP_COMMIT();
    };

    prefetch(0);
    prefetch(1);

    float acc[3][4][4] = {};

    #pragma unroll
    for (int it = 0; it < NIT; it++) {
        if (it < NIT - 1) asm volatile("cp.async.wait_group 1;");
        else              asm volatile("cp.async.wait_group 0;");
        __syncthreads();
        if (it + 2 < NIT) prefetch(it + 2);

        const int s = it % 3;
        const uint32_t stA = bA + s * SA_BYTES;
        const uint32_t stB = bB + s * SB_BYTES;
        #pragma unroll
        for (int ks = 0; ks < 2; ks++) {
            uint32_t Bf[4][2];
            #pragma unroll
            for (int jj = 0; jj < 2; jj++) {
                uint32_t r[4];
                uint32_t off = (((lane & 15) + ks * 16) * PB +
                                warp_n + jj * 16 + (lane >> 4) * 8) * 2;
                ldsm4t(r, stB + off);
                Bf[2 * jj][0] = r[0]; Bf[2 * jj][1] = r[1];
                Bf[2 * jj + 1][0] = r[2]; Bf[2 * jj + 1][1] = r[3];
            }
            #pragma unroll
            for (int i = 0; i < 3; i++) {
                uint32_t Af[4];
                ldsm4(Af, stA + aOff + i * (16 * PA * 2) + ks * 32);
                #pragma unroll
                for (int j = 0; j < 4; j++)
                    mma_f16(acc[i][j], Af, Bf[j]);
            }
        }
    }

    #pragma unroll
    for (int i = 0; i < 3; i++) {
        int m = o0 + warp_m + i * 16 + (lane >> 2);
        float bv0 = bias[m], bv1 = bias[m + 8];
        #pragma unroll
        for (int j = 0; j < 4; j++) {
            int n = n0 + warp_n + j * 8 + (lane & 3) * 2;
            if (OHALF) {
                __half* Y = (__half*)Yall + (size_t)blockIdx.z * ybs;
                __half2 r0 = __floats2half2_rn(acc[i][j][0] + bv0, acc[i][j][1] + bv0);
                __half2 r1 = __floats2half2_rn(acc[i][j][2] + bv1, acc[i][j][3] + bv1);
                *reinterpret_cast<__half2*>(&Y[(size_t)m * NPTS + n]) = r0;
                *reinterpret_cast<__half2*>(&Y[(size_t)(m + 8) * NPTS + n]) = r1;
            } else {
                float* Y = (float*)Yall + (size_t)blockIdx.z * ybs;
                float2 r0 = {acc[i][j][0] + bv0, acc[i][j][1] + bv0};
                float2 r1 = {acc[i][j][2] + bv1, acc[i][j][3] + bv1};
                *reinterpret_cast<float2*>(&Y[(size_t)m * NPTS + n]) = r0;
                *reinterpret_cast<float2*>(&Y[(size_t)(m + 8) * NPTS + n]) = r1;
            }
        }
    }
}

// ---------------- depthwise 3x3x3: z-rotation + packed fp32x2 FMA ------------------
__global__ __launch_bounds__(256) void dwconv3(
    const __half* __restrict__ in, const float* __restrict__ w,
    const float* __restrict__ bias, __half* __restrict__ outh,
    float* __restrict__ ssq)
{
    int bc = blockIdx.x;
    int b  = bc / C3;
    int c  = bc % C3;
    const __half* vol = in + (size_t)bc * NPTS;
    __half* op = outh + (size_t)bc * NPTS;

    u64t ww[27];
    #pragma unroll
    for (int i = 0; i < 27; i++) { float wv = w[c * 27 + i]; ww[i] = pk2(wv, wv); }
    float bv = bias[c];
    const u64t bb = pk2(bv, bv);

    __shared__ float P[2][34][36];
    __shared__ float sred[8];
    int tid = threadIdx.x;
    for (int i = tid; i < 2 * 34 * 36; i += 256) ((float*)P)[i] = 0.f;
    __syncthreads();

    const int ly = tid >> 3, lx4 = (tid & 7) * 4;
    {
        uint2 raw = *reinterpret_cast<const uint2*>(&vol[ly * 32 + lx4]);
        __half2 hA = *reinterpret_cast<__half2*>(&raw.x);
        __half2 hB = *reinterpret_cast<__half2*>(&raw.y);
        P[0][1 + ly][1 + lx4 + 0] = __half2float(hA.x);
        P[0][1 + ly][1 + lx4 + 1] = __half2float(hA.y);
        P[0][1 + ly][1 + lx4 + 2] = __half2float(hB.x);
        P[0][1 + ly][1 + lx4 + 3] = __half2float(hB.y);
    }
    __syncthreads();

    float qs = 0.f;
    const bool is_qk = (c < 2 * C);

    u64t a0L = bb, a0H = bb, a1L = bb, a1H = bb;

    for (int z = 0; z < SDIM; z++) {
        uint2 raw;
        if (z + 1 < SDIM)
            raw = *reinterpret_cast<const uint2*>(&vol[(size_t)(z + 1) * 1024 + ly * 32 + lx4]);

        u64t cdL[3] = {0, 0, 0}, cdH[3] = {0, 0, 0};
        const int s = z & 1;
        #pragma unroll
        for (int dy = 0; dy < 3; dy++) {
            const float* row = &P[s][ly + dy][lx4];
            float4 rA = *reinterpret_cast<const float4*>(row);
            float2 rB = *reinterpret_cast<const float2*>(row + 4);
            u64t p0 = pk2(rA.x, rA.y), p1 = pk2(rA.y, rA.z), p2 = pk2(rA.z, rA.w);
            u64t p3 = pk2(rA.w, rB.x), p4 = pk2(rB.x, rB.y);
            #pragma unroll
            for (int dz = 0; dz < 3; dz++) {
                const int base = dz * 9 + dy * 3;
                fma2(cdL[dz], ww[base + 0], p0);
                fma2(cdL[dz], ww[base + 1], p1);
                fma2(cdL[dz], ww[base + 2], p2);
                fma2(cdH[dz], ww[base + 0], p2);
                fma2(cdH[dz], ww[base + 1], p3);
                fma2(cdH[dz], ww[base + 2], p4);
            }
        }

        if (z > 0) {
            u64t oL = add2(a0L, cdL[2]);
            u64t oH = add2(a0H, cdH[2]);
            float o0, o1, o2, o3;
            upk2(oL, o0, o1); upk2(oH, o2, o3);
            __half2 h0 = __floats2half2_rn(o0, o1);
            __half2 h1 = __floats2half2_rn(o2, o3);
            uint2 hv = {*reinterpret_cast<uint32_t*>(&h0), *reinterpret_cast<uint32_t*>(&h1)};
            *reinterpret_cast<uint2*>(&op[(size_t)(z - 1) * 1024 + ly * 32 + lx4]) = hv;
            if (is_qk) {
                float r0 = __half2float(h0.x), r1 = __half2float(h0.y);
                float r2 = __half2float(h1.x), r3 = __half2float(h1.y);
                qs += r0 * r0 + r1 * r1 + r2 * r2 + r3 * r3;
            }
        }
        a0L = add2(a1L, cdL[1]); a0H = add2(a1H, cdH[1]);
        a1L = add2(bb, cdL[0]);  a1H = add2(bb, cdH[0]);

        if (z + 1 < SDIM) {
            __half2 hA = *reinterpret_cast<__half2*>(&raw.x);
            __half2 hB = *reinterpret_cast<__half2*>(&raw.y);
            P[s ^ 1][1 + ly][1 + lx4 + 0] = __half2float(hA.x);
            P[s ^ 1][1 + ly][1 + lx4 + 1] = __half2float(hA.y);
            P[s ^ 1][1 + ly][1 + lx4 + 2] = __half2float(hB.x);
            P[s ^ 1][1 + ly][1 + lx4 + 3] = __half2float(hB.y);
        }
        __syncthreads();
    }
    {
        float o0, o1, o2, o3;
        upk2(a0L, o0, o1); upk2(a0H, o2, o3);
        __half2 h0 = __floats2half2_rn(o0, o1);
        __half2 h1 = __floats2half2_rn(o2, o3);
        uint2 hv = {*reinterpret_cast<uint32_t*>(&h0), *reinterpret_cast<uint32_t*>(&h1)};
        *reinterpret_cast<uint2*>(&op[(size_t)31 * 1024 + ly * 32 + lx4]) = hv;
        if (is_qk) {
            float r0 = __half2float(h0.x), r1 = __half2float(h0.y);
            float r2 = __half2float(h1.x), r3 = __half2float(h1.y);
            qs += r0 * r0 + r1 * r1 + r2 * r2 + r3 * r3;
        }
    }

    if (is_qk) {
        #pragma unroll
        for (int o = 16; o > 0; o >>= 1) qs += __shfl_xor_sync(~0u, qs, o);
        if ((tid & 31) == 0) sred[tid >> 5] = qs;
        __syncthreads();
        if (tid < 8) {
            float v = sred[tid];
            #pragma unroll
            for (int o = 4; o > 0; o >>= 1) v += __shfl_xor_sync(0xffu, v, o);
            if (tid == 0) ssq[b * 2 * C + c] = v;
        }
    }
}

// ---------------- q @ k^T via fp16 mma.sync ----------------
#define QKC 128
#define QKP 136
#define QK_ARR (48 * QKP * 2)
#define QK_STAGE (2 * QK_ARR)
#define QK_NSPL 32
#define QK_SLAB (NPTS / QK_NSPL)     // 1024
#define QK_SMEM (2 * QK_STAGE + 48 * 49 * 4)

__global__ __launch_bounds__(256) void qk_mma(
    const __half* __restrict__ dwh, float* __restrict__ attn)
{
    extern __shared__ char smem[];
    float* sAcc = reinterpret_cast<float*>(smem + 2 * QK_STAGE);
    const int tid = threadIdx.x, wid = tid >> 5, lane = tid & 31;
    const int b = blockIdx.z, h = blockIdx.y;
    const int n0 = blockIdx.x * QK_SLAB;

    const __half* srcs[2] = {
        dwh + ((size_t)b * C3 + h * CH) * NPTS,
        dwh + ((size_t)b * C3 + C + h * CH) * NPTS
    };
    const uint32_t sbase = smem_u32(smem);

    for (int i = tid; i < 48 * 49; i += 256) sAcc[i] = 0.f;

    int la[6], lr[6], lc[6];
    #pragma unroll
    for (int q = 0; q < 6; q++) {
        int idx = tid + q * 256;
        la[q] = idx / 768;
        int rem = idx % 768;
        lr[q] = rem / 16;
        lc[q] = (rem % 16) * 8;
    }

    const int NCH = QK_SLAB / QKC;   // 8
    #pragma unroll
    for (int q = 0; q < 6; q++) {
        uint32_t dst = sbase + la[q] * QK_ARR + (lr[q] * QKP + lc[q]) * 2;
        CP_CG16(dst, srcs[la[q]] + (size_t)lr[q] * NPTS + n0 + lc[q]);
    }
    CP_COMMIT();

    float acc[3][6][4] = {};
    const int k0 = wid * 16;

    for (int ch = 0; ch < NCH; ch++) {
        if (ch + 1 < NCH) {
            uint32_t st = ((ch + 1) & 1) * QK_STAGE;
            int nb = n0 + (ch + 1) * QKC;
            #pragma unroll
            for (int q = 0; q < 6; q++) {
                uint32_t dst = sbase + st + la[q] * QK_ARR + (lr[q] * QKP + lc[q]) * 2;
                CP_CG16(dst, srcs[la[q]] + (size_t)lr[q] * NPTS + nb + lc[q]);
            }
            CP_COMMIT();
            asm volatile("cp.async.wait_group 1;");
        } else {
            asm volatile("cp.async.wait_group 0;");
        }
        __syncthreads();

        const uint32_t st = sbase + (ch & 1) * QK_STAGE;
        uint32_t Af[3][4], Bf[6][2];
        #pragma unroll
        for (int i = 0; i < 3; i++) {
            uint32_t off = ((i * 16 + (lane & 15)) * QKP + k0 + (lane >> 4) * 8) * 2;
            ldsm4(Af[i], st + off);
        }
        #pragma unroll
        for (int jj = 0; jj < 3; jj++) {
            uint32_t r[4];
            uint32_t off = ((jj * 16 + (lane & 7) + ((lane >> 4) << 3)) * QKP +
                            k0 + ((lane >> 3) & 1) * 8) * 2;
            ldsm4(r, st + QK_ARR + off);
            Bf[2 * jj][0] = r[0]; Bf[2 * jj][1] = r[1];
            Bf[2 * jj + 1][0] = r[2]; Bf[2 * jj + 1][1] = r[3];
        }
        #pragma unroll
        for (int i = 0; i < 3; i++)
            #pragma unroll
            for (int j = 0; j < 6; j++)
                mma_f16(acc[i][j], Af[i], Bf[j]);
        __syncthreads();
    }

    #pragma unroll
    for (int i = 0; i < 3; i++) {
        int m = i * 16 + (lane >> 2);
        #pragma unroll
        for (int j = 0; j < 6; j++) {
            int n = j * 8 + (lane & 3) * 2;
            atomicAdd(&sAcc[m * 49 + n],           acc[i][j][0]);
            atomicAdd(&sAcc[m * 49 + n + 1],       acc[i][j][1]);
            atomicAdd(&sAcc[(m + 8) * 49 + n],     acc[i][j][2]);
            atomicAdd(&sAcc[(m + 8) * 49 + n + 1], acc[i][j][3]);
        }
    }
    __syncthreads();
    float* dst = attn + (size_t)(b * HEADS + h) * CH * CH;
    for (int i = tid; i < CH * CH; i += 256)
        atomicAdd(&dst[i], sAcc[(i / CH) * 49 + (i % CH)]);
}

// ---------------- fused softmax + proj∘attn weight build (8 blocks, 192 thr) -------
__global__ __launch_bounds__(192) void smfuse(
    const float* __restrict__ attn, const float* __restrict__ ssq,
    const float* __restrict__ temp, const float* __restrict__ proj_w,
    __half* __restrict__ w2)
{
    int bh = blockIdx.x;
    int h = bh % HEADS, b = bh / HEADS;
    __shared__ float At[CH][CH];           // post-softmax attn [c][e]
    const float* am = attn + (size_t)bh * CH * CH;
    const float t = temp[h];

    // phase 1: softmax; 4 threads per row, 12 e-values each
    {
        int c = threadIdx.x >> 2, qq = threadIdx.x & 3;
        float iq = 1.f / fmaxf(sqrtf(ssq[b * 2 * C + h * CH + c]), EPS);
        float xv[12];
        float mx = -1e30f;
        #pragma unroll
        for (int u = 0; u < 12; u++) {
            int e = qq * 12 + u;
            float ik = 1.f / fmaxf(sqrtf(ssq[b * 2 * C + C + h * CH + e]), EPS);
            xv[u] = am[c * CH + e] * iq * ik * t;
            mx = fmaxf(mx, xv[u]);
        }
        mx = fmaxf(mx, __shfl_xor_sync(~0u, mx, 1));
        mx = fmaxf(mx, __shfl_xor_sync(~0u, mx, 2));
        float sm = 0.f;
        #pragma unroll
        for (int u = 0; u < 12; u++) { xv[u] = expf(xv[u] - mx); sm += xv[u]; }
        sm += __shfl_xor_sync(~0u, sm, 1);
        sm += __shfl_xor_sync(~0u, sm, 2);
        float r = 1.f / sm;
        #pragma unroll
        for (int u = 0; u < 12; u++) At[c][qq * 12 + u] = xv[u] * r;
    }
    __syncthreads();

    // phase 2: w2[b][o][h*48+e] = sum_c proj[o, h*48+c] * At[c][e]
    int o = threadIdx.x;
    float pr[CH];
    #pragma unroll
    for (int c = 0; c < CH; c++) pr[c] = proj_w[(size_t)o * C + h * CH + c];

    __half* dst = w2 + (size_t)b * C * C + (size_t)o * C + h * CH;
    #pragma unroll 4
    for (int e = 0; e < CH; e++) {
        float acc = 0.f;
        #pragma unroll
        for (int c = 0; c < CH; c++) acc += pr[c] * At[c][e];
        dst[e] = __float2half_rn(acc);
    }
}

// ---------------- launch ----------------
extern "C" void kernel_launch(void* const* d_in, const int* in_sizes, int n_in,
                              void* d_out, int out_size)
{
    const float* x      = (const float*)d_in[0];
    const float* qkv_w  = (const float*)d_in[1];
    const float* qkv_b  = (const float*)d_in[2];
    const float* dw_w   = (const float*)d_in[3];
    const float* dw_b   = (const float*)d_in[4];
    const float* proj_w = (const float*)d_in[5];
    const float* proj_b = (const float*)d_in[6];
    const float* temp   = (const float*)d_in[7];
    float* out = (float*)d_out;

    float *ssqp, *atp;
    __half *xhp, *qkvhp, *dwhp, *whp, *w2p;
    cudaGetSymbolAddress((void**)&xhp,   g_xh);
    cudaGetSymbolAddress((void**)&qkvhp, g_qkvh);
    cudaGetSymbolAddress((void**)&dwhp,  g_dwh);
    cudaGetSymbolAddress((void**)&ssqp,  g_ssq);
    cudaGetSymbolAddress((void**)&atp,   g_at);
    cudaGetSymbolAddress((void**)&whp,   g_wh);
    cudaGetSymbolAddress((void**)&w2p,   g_w2h);

    cudaFuncSetAttribute(qk_mma, cudaFuncAttributeMaxDynamicSharedMemorySize, QK_SMEM);
    cudaFuncSetAttribute(gemm_mma<1>, cudaFuncAttributeMaxDynamicSharedMemorySize, GM_SMEM);
    cudaFuncSetAttribute(gemm_mma<0>, cudaFuncAttributeMaxDynamicSharedMemorySize, GM_SMEM);

    const size_t SETUP_N = XG + (size_t)C3 * C + B * HEADS * CH * CH;
    // 1) unified setup (x->fp16, W->fp16, zero attn)
    setupk<<<(int)((SETUP_N + 255) / 256), 256>>>(x, xhp, qkv_w, whp, atp);
    // 2) qkv 1x1 conv
    gemm_mma<1><<<dim3(C3 / BMg, NPTS / BNg, B), 256, GM_SMEM>>>(
        xhp, (size_t)C * NPTS, whp, 0, qkv_b, qkvhp, (size_t)C3 * NPTS);
    // 3) depthwise 3x3x3
    dwconv3<<<B * C3, 256>>>(qkvhp, dw_w, dw_b, dwhp, ssqp);
    // 4) q @ k^T (NSPL=32 restored) <- PROFILED
    qk_mma<<<dim3(QK_NSPL, HEADS, B), 256, QK_SMEM>>>(dwhp, atp);
    // 5) fused softmax + proj∘attn weights
    smfuse<<<B * HEADS, 192>>>(atp, ssqp, temp, proj_w, w2p);
    // 6) fused (proj∘attn) @ v
    gemm_mma<0><<<dim3(C / BMg, NPTS / BNg, B), 256, GM_SMEM>>>(
        dwhp + (size_t)2 * C * NPTS, (size_t)C3 * NPTS,
        w2p, (size_t)C * C, proj_b, out, (size_t)C * NPTS);
}

// round 16
// speedup vs baseline: 1.0685x; 1.0220x over previous
#include <cuda_runtime.h>
#include <cuda_fp16.h>
#include <cstdint>

#define B 2
#define C 192
#define C3 576
#define SDIM 32
#define NPTS 32768           // 32^3
#define HEADS 4
#define CH 48
#define EPS 1e-12f

// ---------------- scratch (static device allocations) ----------------
__device__ __half g_xh  [(size_t)B * C * NPTS];      // input x in fp16
__device__ __half g_qkvh[(size_t)B * C3 * NPTS];     // after 1x1 conv (fp16)
__device__ __half g_dwh [(size_t)B * C3 * NPTS];     // after dwconv: q,k,v fp16
__device__ float  g_ssq[B * 2 * C];                  // sum of squares of ROUNDED q/k
__device__ float  g_at [B * HEADS * CH * CH];        // attention logits / probs
__device__ __half g_wh [C3 * C];                     // qkv weights fp16
__device__ __half g_w2h[B * C * C];                  // fused proj∘attn weights fp16

// ================= mma.sync helpers =================
__device__ __forceinline__ uint32_t smem_u32(const void* p) {
    uint32_t a;
    asm("{ .reg .u64 t; cvta.to.shared.u64 t, %1; cvt.u32.u64 %0, t; }" : "=r"(a) : "l"(p));
    return a;
}
__device__ __forceinline__ void ldsm4(uint32_t* r, uint32_t a) {
    asm volatile("ldmatrix.sync.aligned.m8n8.x4.shared.b16 {%0,%1,%2,%3}, [%4];"
                 : "=r"(r[0]), "=r"(r[1]), "=r"(r[2]), "=r"(r[3]) : "r"(a));
}
__device__ __forceinline__ void ldsm4t(uint32_t* r, uint32_t a) {
    asm volatile("ldmatrix.sync.aligned.m8n8.x4.trans.shared.b16 {%0,%1,%2,%3}, [%4];"
                 : "=r"(r[0]), "=r"(r[1]), "=r"(r[2]), "=r"(r[3]) : "r"(a));
}
__device__ __forceinline__ void mma_f16(float* d, const uint32_t* a, const uint32_t* b) {
    asm volatile(
        "mma.sync.aligned.m16n8k16.row.col.f32.f16.f16.f32 "
        "{%0,%1,%2,%3}, {%4,%5,%6,%7}, {%8,%9}, {%0,%1,%2,%3};"
        : "+f"(d[0]), "+f"(d[1]), "+f"(d[2]), "+f"(d[3])
        : "r"(a[0]), "r"(a[1]), "r"(a[2]), "r"(a[3]), "r"(b[0]), "r"(b[1]));
}
#define CP_CG16(dst, src) \
    asm volatile("cp.async.cg.shared.global [%0], [%1], 16;" :: "r"(dst), "l"(src))
#define CP_COMMIT() asm volatile("cp.async.commit_group;")

// ================= packed fp32x2 helpers (sm_100+ family) =================
typedef unsigned long long u64t;
__device__ __forceinline__ u64t pk2(float lo, float hi) {
    u64t d;
    asm("mov.b64 %0, {%1, %2};" : "=l"(d) : "f"(lo), "f"(hi));
    return d;
}
__device__ __forceinline__ void upk2(u64t d, float& lo, float& hi) {
    asm("mov.b64 {%0, %1}, %2;" : "=f"(lo), "=f"(hi) : "l"(d));
}
__device__ __forceinline__ void fma2(u64t& a, u64t x, u64t y) {
    asm("fma.rn.f32x2 %0, %1, %2, %0;" : "+l"(a) : "l"(x), "l"(y));
}
__device__ __forceinline__ u64t add2(u64t x, u64t y) {
    u64t d;
    asm("add.rn.f32x2 %0, %1, %2;" : "=l"(d) : "l"(x), "l"(y));
    return d;
}

// ---------------- unified setup: x->fp16, W->fp16, zero attn ----------------
#define XG ((size_t)B * C * NPTS / 4)              // float4 groups in x
__global__ void setupk(const float* __restrict__ x, __half* __restrict__ xh,
                       const float* __restrict__ qkv_w, __half* __restrict__ wh,
                       float* __restrict__ attn)
{
    size_t i = (size_t)blockIdx.x * 256 + threadIdx.x;
    if (i < XG) {
        size_t j = i * 4;
        float4 v = *reinterpret_cast<const float4*>(&x[j]);
        __half2 h0 = __floats2half2_rn(v.x, v.y);
        __half2 h1 = __floats2half2_rn(v.z, v.w);
        uint2 r = {*reinterpret_cast<uint32_t*>(&h0), *reinterpret_cast<uint32_t*>(&h1)};
        *reinterpret_cast<uint2*>(&xh[j]) = r;
    } else if (i < XG + (size_t)C3 * C) {
        int j = (int)(i - XG);
        wh[j] = __float2half_rn(qkv_w[j]);
    } else if (i < XG + (size_t)C3 * C + B * HEADS * CH * CH) {
        attn[i - XG - (size_t)C3 * C] = 0.f;
    }
}

// ---------------- 1x1 conv GEMM via fp16 mma.sync, 3-stage cp.async.cg ------------
#define BMg 96
#define BNg 128
#define BKg 32
#define PA 40
#define PB 136
#define SA_BYTES (BMg * PA * 2)      // 7680
#define SB_BYTES (BKg * PB * 2)      // 8704
#define GM_SMEM  (3 * (SA_BYTES + SB_BYTES))   // 49152
#define NIT (C / BKg)                // 6

template<int OHALF>
__global__ __launch_bounds__(256, 2) void gemm_mma(
    const __half* __restrict__ Xall, size_t xbs,
    const __half* __restrict__ WH, size_t wbs,
    const float* __restrict__ bias, void* __restrict__ Yall, size_t ybs)
{
    extern __shared__ char gsm[];
    const int tid = threadIdx.x, wid = tid >> 5, lane = tid & 31;
    const int o0 = blockIdx.x * BMg;
    const int n0 = blockIdx.y * BNg;
    const __half* X = Xall + (size_t)blockIdx.z * xbs;
    const __half* W = WH + (size_t)blockIdx.z * wbs;

    const int warp_m = (wid >> 2) * 48;
    const int warp_n = (wid & 3) * 32;

    const uint32_t bA = smem_u32(gsm);
    const uint32_t bB = bA + 3 * SA_BYTES;
    const uint32_t aOff = ((warp_m + (lane & 15)) * PA + (lane >> 4) * 8) * 2;

    const int ar0 = tid >> 2,        ac0 = (tid & 3) * 8;
    const int ar1 = 64 + (tid >> 2), ac1 = (tid & 3) * 8;
    const int br0 = tid >> 4,        bc0 = (tid & 15) * 8;
    const int br1 = 16 + (tid >> 4), bc1 = (tid & 15) * 8;

    auto prefetch = [&](int it) {
        const int kc = it * BKg;
        const int s  = it % 3;
        const uint32_t dA = bA + s * SA_BYTES;
        const uint32_t dB = bB + s * SB_BYTES;
        CP_CG16(dA + (ar0 * PA + ac0) * 2, &W[(size_t)(o0 + ar0) * C + kc + ac0]);
        if (tid < 128)
            CP_CG16(dA + (ar1 * PA + ac1) * 2, &W[(size_t)(o0 + ar1) * C + kc + ac1]);
        CP_CG16(dB + (br0 * PB + bc0) * 2, &X[(size_t)(kc + br0) * NPTS + n0 + bc0]);
        CP_CG16(dB + (br1 * PB + bc1) * 2, &X[(size_t)(kc + br1) * NPTS + n0 + bc1]);
        CP_COMMIT();
    };

    prefetch(0);
    prefetch(1);

    float acc[3][4][4] = {};

    #pragma unroll
    for (int it = 0; it < NIT; it++) {
        if (it < NIT - 1) asm volatile("cp.async.wait_group 1;");
        else              asm volatile("cp.async.wait_group 0;");
        __syncthreads();
        if (it + 2 < NIT) prefetch(it + 2);

        const int s = it % 3;
        const uint32_t stA = bA + s * SA_BYTES;
        const uint32_t stB = bB + s * SB_BYTES;
        #pragma unroll
        for (int ks = 0; ks < 2; ks++) {
            uint32_t Bf[4][2];
            #pragma unroll
            for (int jj = 0; jj < 2; jj++) {
                uint32_t r[4];
                uint32_t off = (((lane & 15) + ks * 16) * PB +
                                warp_n + jj * 16 + (lane >> 4) * 8) * 2;
                ldsm4t(r, stB + off);
                Bf[2 * jj][0] = r[0]; Bf[2 * jj][1] = r[1];
                Bf[2 * jj + 1][0] = r[2]; Bf[2 * jj + 1][1] = r[3];
            }
            #pragma unroll
            for (int i = 0; i < 3; i++) {
                uint32_t Af[4];
                ldsm4(Af, stA + aOff + i * (16 * PA * 2) + ks * 32);
                #pragma unroll
                for (int j = 0; j < 4; j++)
                    mma_f16(acc[i][j], Af, Bf[j]);
            }
        }
    }

    #pragma unroll
    for (int i = 0; i < 3; i++) {
        int m = o0 + warp_m + i * 16 + (lane >> 2);
        float bv0 = bias[m], bv1 = bias[m + 8];
        #pragma unroll
        for (int j = 0; j < 4; j++) {
            int n = n0 + warp_n + j * 8 + (lane & 3) * 2;
            if (OHALF) {
                __half* Y = (__half*)Yall + (size_t)blockIdx.z * ybs;
                __half2 r0 = __floats2half2_rn(acc[i][j][0] + bv0, acc[i][j][1] + bv0);
                __half2 r1 = __floats2half2_rn(acc[i][j][2] + bv1, acc[i][j][3] + bv1);
                *reinterpret_cast<__half2*>(&Y[(size_t)m * NPTS + n]) = r0;
                *reinterpret_cast<__half2*>(&Y[(size_t)(m + 8) * NPTS + n]) = r1;
            } else {
                float* Y = (float*)Yall + (size_t)blockIdx.z * ybs;
                float2 r0 = {acc[i][j][0] + bv0, acc[i][j][1] + bv0};
                float2 r1 = {acc[i][j][2] + bv1, acc[i][j][3] + bv1};
                *reinterpret_cast<float2*>(&Y[(size_t)m * NPTS + n]) = r0;
                *reinterpret_cast<float2*>(&Y[(size_t)(m + 8) * NPTS + n]) = r1;
            }
        }
    }
}

// ---------------- depthwise 3x3x3: 2 planes/iter, 4-slot ring, fp32x2 FMA ----------
__global__ __launch_bounds__(256) void dwconv3(
    const __half* __restrict__ in, const float* __restrict__ w,
    const float* __restrict__ bias, __half* __restrict__ outh,
    float* __restrict__ ssq)
{
    int bc = blockIdx.x;
    int b  = bc / C3;
    int c  = bc % C3;
    const __half* vol = in + (size_t)bc * NPTS;
    __half* op = outh + (size_t)bc * NPTS;

    u64t ww[27];
    #pragma unroll
    for (int i = 0; i < 27; i++) { float wv = w[c * 27 + i]; ww[i] = pk2(wv, wv); }
    float bv = bias[c];
    const u64t bb = pk2(bv, bv);

    __shared__ float P[4][34][36];
    __shared__ float sred[8];
    int tid = threadIdx.x;
    for (int i = tid; i < 4 * 34 * 36; i += 256) ((float*)P)[i] = 0.f;
    __syncthreads();

    const int ly = tid >> 3, lx4 = (tid & 7) * 4;
    auto stage = [&](uint2 raw, int slot) {
        __half2 hA = *reinterpret_cast<__half2*>(&raw.x);
        __half2 hB = *reinterpret_cast<__half2*>(&raw.y);
        P[slot][1 + ly][1 + lx4 + 0] = __half2float(hA.x);
        P[slot][1 + ly][1 + lx4 + 1] = __half2float(hA.y);
        P[slot][1 + ly][1 + lx4 + 2] = __half2float(hB.x);
        P[slot][1 + ly][1 + lx4 + 3] = __half2float(hB.y);
    };

    {   // prologue: planes 0,1 -> slots 0,1
        uint2 r0 = *reinterpret_cast<const uint2*>(&vol[ly * 32 + lx4]);
        uint2 r1 = *reinterpret_cast<const uint2*>(&vol[(size_t)1024 + ly * 32 + lx4]);
        stage(r0, 0);
        stage(r1, 1);
    }
    __syncthreads();

    float qs = 0.f;
    const bool is_qk = (c < 2 * C);

    u64t a0L = bb, a0H = bb, a1L = bb, a1H = bb;

    // one compute step for plane p staged in slot s; stores out[p-1] if p>0
    auto plane_step = [&](int p, int s) {
        u64t cdL[3] = {0, 0, 0}, cdH[3] = {0, 0, 0};
        #pragma unroll
        for (int dy = 0; dy < 3; dy++) {
            const float* row = &P[s][ly + dy][lx4];
            float4 rA = *reinterpret_cast<const float4*>(row);
            float2 rB = *reinterpret_cast<const float2*>(row + 4);
            u64t p0 = pk2(rA.x, rA.y), p1 = pk2(rA.y, rA.z), p2 = pk2(rA.z, rA.w);
            u64t p3 = pk2(rA.w, rB.x), p4 = pk2(rB.x, rB.y);
            #pragma unroll
            for (int dz = 0; dz < 3; dz++) {
                const int base = dz * 9 + dy * 3;
                fma2(cdL[dz], ww[base + 0], p0);
                fma2(cdL[dz], ww[base + 1], p1);
                fma2(cdL[dz], ww[base + 2], p2);
                fma2(cdH[dz], ww[base + 0], p2);
                fma2(cdH[dz], ww[base + 1], p3);
                fma2(cdH[dz], ww[base + 2], p4);
            }
        }
        if (p > 0) {
            u64t oL = add2(a0L, cdL[2]);
            u64t oH = add2(a0H, cdH[2]);
            float o0, o1, o2, o3;
            upk2(oL, o0, o1); upk2(oH, o2, o3);
            __half2 h0 = __floats2half2_rn(o0, o1);
            __half2 h1 = __floats2half2_rn(o2, o3);
            uint2 hv = {*reinterpret_cast<uint32_t*>(&h0), *reinterpret_cast<uint32_t*>(&h1)};
            *reinterpret_cast<uint2*>(&op[(size_t)(p - 1) * 1024 + ly * 32 + lx4]) = hv;
            if (is_qk) {
                float r0 = __half2float(h0.x), r1 = __half2float(h0.y);
                float r2 = __half2float(h1.x), r3 = __half2float(h1.y);
                qs += r0 * r0 + r1 * r1 + r2 * r2 + r3 * r3;
            }
        }
        a0L = add2(a1L, cdL[1]); a0H = add2(a1H, cdH[1]);
        a1L = add2(bb, cdL[0]);  a1H = add2(bb, cdH[0]);
    };

    for (int t = 0; t < SDIM / 2; t++) {
        const int p0 = 2 * t, p1 = 2 * t + 1;
        uint2 r2, r3;
        const bool has2 = (p0 + 2 < SDIM), has3 = (p1 + 2 < SDIM);
        if (has2) r2 = *reinterpret_cast<const uint2*>(&vol[(size_t)(p0 + 2) * 1024 + ly * 32 + lx4]);
        if (has3) r3 = *reinterpret_cast<const uint2*>(&vol[(size_t)(p1 + 2) * 1024 + ly * 32 + lx4]);

        plane_step(p0, p0 & 3);
        plane_step(p1, p1 & 3);

        if (has2) stage(r2, (p0 + 2) & 3);
        if (has3) stage(r3, (p1 + 2) & 3);
        __syncthreads();
    }
    {   // out[31]: dz=2 contribution is zero padding
        float o0, o1, o2, o3;
        upk2(a0L, o0, o1); upk2(a0H, o2, o3);
        __half2 h0 = __floats2half2_rn(o0, o1);
        __half2 h1 = __floats2half2_rn(o2, o3);
        uint2 hv = {*reinterpret_cast<uint32_t*>(&h0), *reinterpret_cast<uint32_t*>(&h1)};
        *reinterpret_cast<uint2*>(&op[(size_t)31 * 1024 + ly * 32 + lx4]) = hv;
        if (is_qk) {
            float r0 = __half2float(h0.x), r1 = __half2float(h0.y);
            float r2 = __half2float(h1.x), r3 = __half2float(h1.y);
            qs += r0 * r0 + r1 * r1 + r2 * r2 + r3 * r3;
        }
    }

    if (is_qk) {
        #pragma unroll
        for (int o = 16; o > 0; o >>= 1) qs += __shfl_xor_sync(~0u, qs, o);
        if ((tid & 31) == 0) sred[tid >> 5] = qs;
        __syncthreads();
        if (tid < 8) {
            float v = sred[tid];
            #pragma unroll
            for (int o = 4; o > 0; o >>= 1) v += __shfl_xor_sync(0xffu, v, o);
            if (tid == 0) ssq[b * 2 * C + c] = v;
        }
    }
}

// ---------------- q @ k^T via fp16 mma.sync, 3-stage cp.async ----------------
#define QKC 128
#define QKP 136
#define QK_ARR (48 * QKP * 2)
#define QK_STAGE (2 * QK_ARR)
#define QK_NSPL 32
#define QK_SLAB (NPTS / QK_NSPL)     // 1024
#define QK_SMEM (3 * QK_STAGE + 48 * 49 * 4)

__global__ __launch_bounds__(256) void qk_mma(
    const __half* __restrict__ dwh, float* __restrict__ attn)
{
    extern __shared__ char smem[];
    float* sAcc = reinterpret_cast<float*>(smem + 3 * QK_STAGE);
    const int tid = threadIdx.x, wid = tid >> 5, lane = tid & 31;
    const int b = blockIdx.z, h = blockIdx.y;
    const int n0 = blockIdx.x * QK_SLAB;

    const __half* srcs[2] = {
        dwh + ((size_t)b * C3 + h * CH) * NPTS,
        dwh + ((size_t)b * C3 + C + h * CH) * NPTS
    };
    const uint32_t sbase = smem_u32(smem);

    for (int i = tid; i < 48 * 49; i += 256) sAcc[i] = 0.f;

    int la[6], lr[6], lc[6];
    #pragma unroll
    for (int q = 0; q < 6; q++) {
        int idx = tid + q * 256;
        la[q] = idx / 768;
        int rem = idx % 768;
        lr[q] = rem / 16;
        lc[q] = (rem % 16) * 8;
    }

    const int NCH = QK_SLAB / QKC;   // 8
    auto prefetch = [&](int ch) {
        uint32_t st = (uint32_t)(ch % 3) * QK_STAGE;
        int nb = n0 + ch * QKC;
        #pragma unroll
        for (int q = 0; q < 6; q++) {
            uint32_t dst = sbase + st + la[q] * QK_ARR + (lr[q] * QKP + lc[q]) * 2;
            CP_CG16(dst, srcs[la[q]] + (size_t)lr[q] * NPTS + nb + lc[q]);
        }
        CP_COMMIT();
    };

    prefetch(0);
    prefetch(1);

    float acc[3][6][4] = {};
    const int k0 = wid * 16;

    for (int ch = 0; ch < NCH; ch++) {
        if (ch < NCH - 1) asm volatile("cp.async.wait_group 1;");
        else              asm volatile("cp.async.wait_group 0;");
        __syncthreads();
        if (ch + 2 < NCH) prefetch(ch + 2);

        const uint32_t st = sbase + (uint32_t)(ch % 3) * QK_STAGE;
        uint32_t Af[3][4], Bf[6][2];
        #pragma unroll
        for (int i = 0; i < 3; i++) {
            uint32_t off = ((i * 16 + (lane & 15)) * QKP + k0 + (lane >> 4) * 8) * 2;
            ldsm4(Af[i], st + off);
        }
        #pragma unroll
        for (int jj = 0; jj < 3; jj++) {
            uint32_t r[4];
            uint32_t off = ((jj * 16 + (lane & 7) + ((lane >> 4) << 3)) * QKP +
                            k0 + ((lane >> 3) & 1) * 8) * 2;
            ldsm4(r, st + QK_ARR + off);
            Bf[2 * jj][0] = r[0]; Bf[2 * jj][1] = r[1];
            Bf[2 * jj + 1][0] = r[2]; Bf[2 * jj + 1][1] = r[3];
        }
        #pragma unroll
        for (int i = 0; i < 3; i++)
            #pragma unroll
            for (int j = 0; j < 6; j++)
                mma_f16(acc[i][j], Af[i], Bf[j]);
    }

    __syncthreads();
    #pragma unroll
    for (int i = 0; i < 3; i++) {
        int m = i * 16 + (lane >> 2);
        #pragma unroll
        for (int j = 0; j < 6; j++) {
            int n = j * 8 + (lane & 3) * 2;
            atomicAdd(&sAcc[m * 49 + n],           acc[i][j][0]);
            atomicAdd(&sAcc[m * 49 + n + 1],       acc[i][j][1]);
            atomicAdd(&sAcc[(m + 8) * 49 + n],     acc[i][j][2]);
            atomicAdd(&sAcc[(m + 8) * 49 + n + 1], acc[i][j][3]);
        }
    }
    __syncthreads();
    float* dst = attn + (size_t)(b * HEADS + h) * CH * CH;
    for (int i = tid; i < CH * CH; i += 256)
        atomicAdd(&dst[i], sAcc[(i / CH) * 49 + (i % CH)]);
}

// ---------------- fused softmax + proj∘attn weight build (8 blocks, 192 thr) -------
__global__ __launch_bounds__(192) void smfuse(
    const float* __restrict__ attn, const float* __restrict__ ssq,
    const float* __restrict__ temp, const float* __restrict__ proj_w,
    __half* __restrict__ w2)
{
    int bh = blockIdx.x;
    int h = bh % HEADS, b = bh / HEADS;
    __shared__ float At[CH][CH];
    const float* am = attn + (size_t)bh * CH * CH;
    const float t = temp[h];

    {
        int c = threadIdx.x >> 2, qq = threadIdx.x & 3;
        float iq = 1.f / fmaxf(sqrtf(ssq[b * 2 * C + h * CH + c]), EPS);
        float xv[12];
        float mx = -1e30f;
        #pragma unroll
        for (int u = 0; u < 12; u++) {
            int e = qq * 12 + u;
            float ik = 1.f / fmaxf(sqrtf(ssq[b * 2 * C + C + h * CH + e]), EPS);
            xv[u] = am[c * CH + e] * iq * ik * t;
            mx = fmaxf(mx, xv[u]);
        }
        mx = fmaxf(mx, __shfl_xor_sync(~0u, mx, 1));
        mx = fmaxf(mx, __shfl_xor_sync(~0u, mx, 2));
        float sm = 0.f;
        #pragma unroll
        for (int u = 0; u < 12; u++) { xv[u] = expf(xv[u] - mx); sm += xv[u]; }
        sm += __shfl_xor_sync(~0u, sm, 1);
        sm += __shfl_xor_sync(~0u, sm, 2);
        float r = 1.f / sm;
        #pragma unroll
        for (int u = 0; u < 12; u++) At[c][qq * 12 + u] = xv[u] * r;
    }
    __syncthreads();

    int o = threadIdx.x;
    float pr[CH];
    #pragma unroll
    for (int c = 0; c < CH; c++) pr[c] = proj_w[(size_t)o * C + h * CH + c];

    __half* dst = w2 + (size_t)b * C * C + (size_t)o * C + h * CH;
    #pragma unroll 4
    for (int e = 0; e < CH; e++) {
        float acc = 0.f;
        #pragma unroll
        for (int c = 0; c < CH; c++) acc += pr[c] * At[c][e];
        dst[e] = __float2half_rn(acc);
    }
}

// ---------------- launch ----------------
extern "C" void kernel_launch(void* const* d_in, const int* in_sizes, int n_in,
                              void* d_out, int out_size)
{
    const float* x      = (const float*)d_in[0];
    const float* qkv_w  = (const float*)d_in[1];
    const float* qkv_b  = (const float*)d_in[2];
    const float* dw_w   = (const float*)d_in[3];
    const float* dw_b   = (const float*)d_in[4];
    const float* proj_w = (const float*)d_in[5];
    const float* proj_b = (const float*)d_in[6];
    const float* temp   = (const float*)d_in[7];
    float* out = (float*)d_out;

    float *ssqp, *atp;
    __half *xhp, *qkvhp, *dwhp, *whp, *w2p;
    cudaGetSymbolAddress((void**)&xhp,   g_xh);
    cudaGetSymbolAddress((void**)&qkvhp, g_qkvh);
    cudaGetSymbolAddress((void**)&dwhp,  g_dwh);
    cudaGetSymbolAddress((void**)&ssqp,  g_ssq);
    cudaGetSymbolAddress((void**)&atp,   g_at);
    cudaGetSymbolAddress((void**)&whp,   g_wh);
    cudaGetSymbolAddress((void**)&w2p,   g_w2h);

    cudaFuncSetAttribute(qk_mma, cudaFuncAttributeMaxDynamicSharedMemorySize, QK_SMEM);
    cudaFuncSetAttribute(gemm_mma<1>, cudaFuncAttributeMaxDynamicSharedMemorySize, GM_SMEM);
    cudaFuncSetAttribute(gemm_mma<0>, cudaFuncAttributeMaxDynamicSharedMemorySize, GM_SMEM);

    const size_t SETUP_N = XG + (size_t)C3 * C + B * HEADS * CH * CH;
    // 1) unified setup (x->fp16, W->fp16, zero attn)
    setupk<<<(int)((SETUP_N + 255) / 256), 256>>>(x, xhp, qkv_w, whp, atp);
    // 2) qkv 1x1 conv
    gemm_mma<1><<<dim3(C3 / BMg, NPTS / BNg, B), 256, GM_SMEM>>>(
        xhp, (size_t)C * NPTS, whp, 0, qkv_b, qkvhp, (size_t)C3 * NPTS);
    // 3) depthwise 3x3x3 (2 planes/iter)
    dwconv3<<<B * C3, 256>>>(qkvhp, dw_w, dw_b, dwhp, ssqp);
    // 4) q @ k^T (3-stage pipeline) <- PROFILED
    qk_mma<<<dim3(QK_NSPL, HEADS, B), 256, QK_SMEM>>>(dwhp, atp);
    // 5) fused softmax + proj∘attn weights
    smfuse<<<B * HEADS, 192>>>(atp, ssqp, temp, proj_w, w2p);
    // 6) fused (proj∘attn) @ v
    gemm_mma<0><<<dim3(C / BMg, NPTS / BNg, B), 256, GM_SMEM>>>(
        dwhp + (size_t)2 * C * NPTS, (size_t)C3 * NPTS,
        w2p, (size_t)C * C, proj_b, out, (size_t)C * NPTS);
}

// round 17
// speedup vs baseline: 1.0794x; 1.0102x over previous
#include <cuda_runtime.h>
#include <cuda_fp16.h>
#include <cstdint>

#define B 2
#define C 192
#define C3 576
#define SDIM 32
#define NPTS 32768           // 32^3
#define HEADS 4
#define CH 48
#define EPS 1e-12f

// ---------------- scratch (static device allocations) ----------------
__device__ __half g_xh  [(size_t)B * C * NPTS];      // input x in fp16
__device__ __half g_qkvh[(size_t)B * C3 * NPTS];     // after 1x1 conv (fp16)
__device__ __half g_dwh [(size_t)B * C3 * NPTS];     // after dwconv: q,k,v fp16
__device__ float  g_ssq[B * 2 * C];                  // sum of squares of ROUNDED q/k
__device__ float  g_at [B * HEADS * CH * CH];        // attention logits / probs
__device__ __half g_wh [C3 * C];                     // qkv weights fp16
__device__ __half g_w2h[B * C * C];                  // fused proj∘attn weights fp16

// ================= mma.sync helpers =================
__device__ __forceinline__ uint32_t smem_u32(const void* p) {
    uint32_t a;
    asm("{ .reg .u64 t; cvta.to.shared.u64 t, %1; cvt.u32.u64 %0, t; }" : "=r"(a) : "l"(p));
    return a;
}
__device__ __forceinline__ void ldsm4(uint32_t* r, uint32_t a) {
    asm volatile("ldmatrix.sync.aligned.m8n8.x4.shared.b16 {%0,%1,%2,%3}, [%4];"
                 : "=r"(r[0]), "=r"(r[1]), "=r"(r[2]), "=r"(r[3]) : "r"(a));
}
__device__ __forceinline__ void ldsm4t(uint32_t* r, uint32_t a) {
    asm volatile("ldmatrix.sync.aligned.m8n8.x4.trans.shared.b16 {%0,%1,%2,%3}, [%4];"
                 : "=r"(r[0]), "=r"(r[1]), "=r"(r[2]), "=r"(r[3]) : "r"(a));
}
__device__ __forceinline__ void mma_f16(float* d, const uint32_t* a, const uint32_t* b) {
    asm volatile(
        "mma.sync.aligned.m16n8k16.row.col.f32.f16.f16.f32 "
        "{%0,%1,%2,%3}, {%4,%5,%6,%7}, {%8,%9}, {%0,%1,%2,%3};"
        : "+f"(d[0]), "+f"(d[1]), "+f"(d[2]), "+f"(d[3])
        : "r"(a[0]), "r"(a[1]), "r"(a[2]), "r"(a[3]), "r"(b[0]), "r"(b[1]));
}
#define CP_CG16(dst, src) \
    asm volatile("cp.async.cg.shared.global [%0], [%1], 16;" :: "r"(dst), "l"(src))
#define CP_COMMIT() asm volatile("cp.async.commit_group;")

// ================= packed fp32x2 helpers (sm_100+ family) =================
typedef unsigned long long u64t;
__device__ __forceinline__ u64t pk2(float lo, float hi) {
    u64t d;
    asm("mov.b64 %0, {%1, %2};" : "=l"(d) : "f"(lo), "f"(hi));
    return d;
}
__device__ __forceinline__ void upk2(u64t d, float& lo, float& hi) {
    asm("mov.b64 {%0, %1}, %2;" : "=f"(lo), "=f"(hi) : "l"(d));
}
__device__ __forceinline__ void fma2(u64t& a, u64t x, u64t y) {
    asm("fma.rn.f32x2 %0, %1, %2, %0;" : "+l"(a) : "l"(x), "l"(y));
}
__device__ __forceinline__ u64t add2(u64t x, u64t y) {
    u64t d;
    asm("add.rn.f32x2 %0, %1, %2;" : "=l"(d) : "l"(x), "l"(y));
    return d;
}

// ---------------- unified setup: x->fp16, W->fp16, zero attn ----------------
#define XG ((size_t)B * C * NPTS / 4)              // float4 groups in x
__global__ void setupk(const float* __restrict__ x, __half* __restrict__ xh,
                       const float* __restrict__ qkv_w, __half* __restrict__ wh,
                       float* __restrict__ attn)
{
    size_t i = (size_t)blockIdx.x * 256 + threadIdx.x;
    if (i < XG) {
        size_t j = i * 4;
        float4 v = *reinterpret_cast<const float4*>(&x[j]);
        __half2 h0 = __floats2half2_rn(v.x, v.y);
        __half2 h1 = __floats2half2_rn(v.z, v.w);
        uint2 r = {*reinterpret_cast<uint32_t*>(&h0), *reinterpret_cast<uint32_t*>(&h1)};
        *reinterpret_cast<uint2*>(&xh[j]) = r;
    } else if (i < XG + (size_t)C3 * C) {
        int j = (int)(i - XG);
        wh[j] = __float2half_rn(qkv_w[j]);
    } else if (i < XG + (size_t)C3 * C + B * HEADS * CH * CH) {
        attn[i - XG - (size_t)C3 * C] = 0.f;
    }
}

// ---------------- 1x1 conv GEMM via fp16 mma.sync, 3-stage cp.async.cg ------------
#define BMg 96
#define BNg 128
#define BKg 32
#define PA 40
#define PB 136
#define SA_BYTES (BMg * PA * 2)      // 7680
#define SB_BYTES (BKg * PB * 2)      // 8704
#define GM_SMEM  (3 * (SA_BYTES + SB_BYTES))   // 49152
#define NIT (C / BKg)                // 6

template<int OHALF>
__global__ __launch_bounds__(256, 2) void gemm_mma(
    const __half* __restrict__ Xall, size_t xbs,
    const __half* __restrict__ WH, size_t wbs,
    const float* __restrict__ bias, void* __restrict__ Yall, size_t ybs)
{
    extern __shared__ char gsm[];
    const int tid = threadIdx.x, wid = tid >> 5, lane = tid & 31;
    const int o0 = blockIdx.x * BMg;
    const int n0 = blockIdx.y * BNg;
    const __half* X = Xall + (size_t)blockIdx.z * xbs;
    const __half* W = WH + (size_t)blockIdx.z * wbs;

    const int warp_m = (wid >> 2) * 48;
    const int warp_n = (wid & 3) * 32;

    const uint32_t bA = smem_u32(gsm);
    const uint32_t bB = bA + 3 * SA_BYTES;
    const uint32_t aOff = ((warp_m + (lane & 15)) * PA + (lane >> 4) * 8) * 2;

    const int ar0 = tid >> 2,        ac0 = (tid & 3) * 8;
    const int ar1 = 64 + (tid >> 2), ac1 = (tid & 3) * 8;
    const int br0 = tid >> 4,        bc0 = (tid & 15) * 8;
    const int br1 = 16 + (tid >> 4), bc1 = (tid & 15) * 8;

    auto prefetch = [&](int it) {
        const int kc = it * BKg;
        const int s  = it % 3;
        const uint32_t dA = bA + s * SA_BYTES;
        const uint32_t dB = bB + s * SB_BYTES;
        CP_CG16(dA + (ar0 * PA + ac0) * 2, &W[(size_t)(o0 + ar0) * C + kc + ac0]);
        if (tid < 128)
            CP_CG16(dA + (ar1 * PA + ac1) * 2, &W[(size_t)(o0 + ar1) * C + kc + ac1]);
        CP_CG16(dB + (br0 * PB + bc0) * 2, &X[(size_t)(kc + br0) * NPTS + n0 + bc0]);
        CP_CG16(dB + (br1 * PB + bc1) * 2, &X[(size_t)(kc + br1) * NPTS + n0 + bc1]);
        CP_COMMIT();
    };

    prefetch(0);
    prefetch(1);

    float acc[3][4][4] = {};

    #pragma unroll
    for (int it = 0; it < NIT; it++) {
        if (it < NIT - 1) asm volatile("cp.async.wait_group 1;");
        else              asm volatile("cp.async.wait_group 0;");
        __syncthreads();
        if (it + 2 < NIT) prefetch(it + 2);

        const int s = it % 3;
        const uint32_t stA = bA + s * SA_BYTES;
        const uint32_t stB = bB + s * SB_BYTES;
        #pragma unroll
        for (int ks = 0; ks < 2; ks++) {
            uint32_t Bf[4][2];
            #pragma unroll
            for (int jj = 0; jj < 2; jj++) {
                uint32_t r[4];
                uint32_t off = (((lane & 15) + ks * 16) * PB +
                                warp_n + jj * 16 + (lane >> 4) * 8) * 2;
                ldsm4t(r, stB + off);
                Bf[2 * jj][0] = r[0]; Bf[2 * jj][1] = r[1];
                Bf[2 * jj + 1][0] = r[2]; Bf[2 * jj + 1][1] = r[3];
            }
            #pragma unroll
            for (int i = 0; i < 3; i++) {
                uint32_t Af[4];
                ldsm4(Af, stA + aOff + i * (16 * PA * 2) + ks * 32);
                #pragma unroll
                for (int j = 0; j < 4; j++)
                    mma_f16(acc[i][j], Af, Bf[j]);
            }
        }
    }

    #pragma unroll
    for (int i = 0; i < 3; i++) {
        int m = o0 + warp_m + i * 16 + (lane >> 2);
        float bv0 = bias[m], bv1 = bias[m + 8];
        #pragma unroll
        for (int j = 0; j < 4; j++) {
            int n = n0 + warp_n + j * 8 + (lane & 3) * 2;
            if (OHALF) {
                __half* Y = (__half*)Yall + (size_t)blockIdx.z * ybs;
                __half2 r0 = __floats2half2_rn(acc[i][j][0] + bv0, acc[i][j][1] + bv0);
                __half2 r1 = __floats2half2_rn(acc[i][j][2] + bv1, acc[i][j][3] + bv1);
                *reinterpret_cast<__half2*>(&Y[(size_t)m * NPTS + n]) = r0;
                *reinterpret_cast<__half2*>(&Y[(size_t)(m + 8) * NPTS + n]) = r1;
            } else {
                float* Y = (float*)Yall + (size_t)blockIdx.z * ybs;
                float2 r0 = {acc[i][j][0] + bv0, acc[i][j][1] + bv0};
                float2 r1 = {acc[i][j][2] + bv1, acc[i][j][3] + bv1};
                *reinterpret_cast<float2*>(&Y[(size_t)m * NPTS + n]) = r0;
                *reinterpret_cast<float2*>(&Y[(size_t)(m + 8) * NPTS + n]) = r1;
            }
        }
    }
}

// ---------------- depthwise 3x3x3: 2 planes/iter, 4-slot ring, fp32x2 FMA ----------
__global__ __launch_bounds__(256) void dwconv3(
    const __half* __restrict__ in, const float* __restrict__ w,
    const float* __restrict__ bias, __half* __restrict__ outh,
    float* __restrict__ ssq)
{
    int bc = blockIdx.x;
    int b  = bc / C3;
    int c  = bc % C3;
    const __half* vol = in + (size_t)bc * NPTS;
    __half* op = outh + (size_t)bc * NPTS;

    u64t ww[27];
    #pragma unroll
    for (int i = 0; i < 27; i++) { float wv = w[c * 27 + i]; ww[i] = pk2(wv, wv); }
    float bv = bias[c];
    const u64t bb = pk2(bv, bv);

    __shared__ float P[4][34][36];
    __shared__ float sred[8];
    int tid = threadIdx.x;
    for (int i = tid; i < 4 * 34 * 36; i += 256) ((float*)P)[i] = 0.f;
    __syncthreads();

    const int ly = tid >> 3, lx4 = (tid & 7) * 4;
    auto stage = [&](uint2 raw, int slot) {
        __half2 hA = *reinterpret_cast<__half2*>(&raw.x);
        __half2 hB = *reinterpret_cast<__half2*>(&raw.y);
        P[slot][1 + ly][1 + lx4 + 0] = __half2float(hA.x);
        P[slot][1 + ly][1 + lx4 + 1] = __half2float(hA.y);
        P[slot][1 + ly][1 + lx4 + 2] = __half2float(hB.x);
        P[slot][1 + ly][1 + lx4 + 3] = __half2float(hB.y);
    };

    {
        uint2 r0 = *reinterpret_cast<const uint2*>(&vol[ly * 32 + lx4]);
        uint2 r1 = *reinterpret_cast<const uint2*>(&vol[(size_t)1024 + ly * 32 + lx4]);
        stage(r0, 0);
        stage(r1, 1);
    }
    __syncthreads();

    float qs = 0.f;
    const bool is_qk = (c < 2 * C);

    u64t a0L = bb, a0H = bb, a1L = bb, a1H = bb;

    auto plane_step = [&](int p, int s) {
        u64t cdL[3] = {0, 0, 0}, cdH[3] = {0, 0, 0};
        #pragma unroll
        for (int dy = 0; dy < 3; dy++) {
            const float* row = &P[s][ly + dy][lx4];
            float4 rA = *reinterpret_cast<const float4*>(row);
            float2 rB = *reinterpret_cast<const float2*>(row + 4);
            u64t p0 = pk2(rA.x, rA.y), p1 = pk2(rA.y, rA.z), p2 = pk2(rA.z, rA.w);
            u64t p3 = pk2(rA.w, rB.x), p4 = pk2(rB.x, rB.y);
            #pragma unroll
            for (int dz = 0; dz < 3; dz++) {
                const int base = dz * 9 + dy * 3;
                fma2(cdL[dz], ww[base + 0], p0);
                fma2(cdL[dz], ww[base + 1], p1);
                fma2(cdL[dz], ww[base + 2], p2);
                fma2(cdH[dz], ww[base + 0], p2);
                fma2(cdH[dz], ww[base + 1], p3);
                fma2(cdH[dz], ww[base + 2], p4);
            }
        }
        if (p > 0) {
            u64t oL = add2(a0L, cdL[2]);
            u64t oH = add2(a0H, cdH[2]);
            float o0, o1, o2, o3;
            upk2(oL, o0, o1); upk2(oH, o2, o3);
            __half2 h0 = __floats2half2_rn(o0, o1);
            __half2 h1 = __floats2half2_rn(o2, o3);
            uint2 hv = {*reinterpret_cast<uint32_t*>(&h0), *reinterpret_cast<uint32_t*>(&h1)};
            *reinterpret_cast<uint2*>(&op[(size_t)(p - 1) * 1024 + ly * 32 + lx4]) = hv;
            if (is_qk) {
                float r0 = __half2float(h0.x), r1 = __half2float(h0.y);
                float r2 = __half2float(h1.x), r3 = __half2float(h1.y);
                qs += r0 * r0 + r1 * r1 + r2 * r2 + r3 * r3;
            }
        }
        a0L = add2(a1L, cdL[1]); a0H = add2(a1H, cdH[1]);
        a1L = add2(bb, cdL[0]);  a1H = add2(bb, cdH[0]);
    };

    for (int t = 0; t < SDIM / 2; t++) {
        const int p0 = 2 * t, p1 = 2 * t + 1;
        uint2 r2, r3;
        const bool has2 = (p0 + 2 < SDIM), has3 = (p1 + 2 < SDIM);
        if (has2) r2 = *reinterpret_cast<const uint2*>(&vol[(size_t)(p0 + 2) * 1024 + ly * 32 + lx4]);
        if (has3) r3 = *reinterpret_cast<const uint2*>(&vol[(size_t)(p1 + 2) * 1024 + ly * 32 + lx4]);

        plane_step(p0, p0 & 3);
        plane_step(p1, p1 & 3);

        if (has2) stage(r2, (p0 + 2) & 3);
        if (has3) stage(r3, (p1 + 2) & 3);
        __syncthreads();
    }
    {
        float o0, o1, o2, o3;
        upk2(a0L, o0, o1); upk2(a0H, o2, o3);
        __half2 h0 = __floats2half2_rn(o0, o1);
        __half2 h1 = __floats2half2_rn(o2, o3);
        uint2 hv = {*reinterpret_cast<uint32_t*>(&h0), *reinterpret_cast<uint32_t*>(&h1)};
        *reinterpret_cast<uint2*>(&op[(size_t)31 * 1024 + ly * 32 + lx4]) = hv;
        if (is_qk) {
            float r0 = __half2float(h0.x), r1 = __half2float(h0.y);
            float r2 = __half2float(h1.x), r3 = __half2float(h1.y);
            qs += r0 * r0 + r1 * r1 + r2 * r2 + r3 * r3;
        }
    }

    if (is_qk) {
        #pragma unroll
        for (int o = 16; o > 0; o >>= 1) qs += __shfl_xor_sync(~0u, qs, o);
        if ((tid & 31) == 0) sred[tid >> 5] = qs;
        __syncthreads();
        if (tid < 8) {
            float v = sred[tid];
            #pragma unroll
            for (int o = 4; o > 0; o >>= 1) v += __shfl_xor_sync(0xffu, v, o);
            if (tid == 0) ssq[b * 2 * C + c] = v;
        }
    }
}

// ---------------- q @ k^T via fp16 mma.sync, 4-stage deep pipeline ----------------
#define QKC 128
#define QKP 136
#define QK_ARR (48 * QKP * 2)
#define QK_STAGE (2 * QK_ARR)
#define QK_NSTG 4
#define QK_NSPL 16
#define QK_SLAB (NPTS / QK_NSPL)     // 2048
#define QK_SMEM (QK_NSTG * QK_STAGE + 48 * 49 * 4)

__global__ __launch_bounds__(256) void qk_mma(
    const __half* __restrict__ dwh, float* __restrict__ attn)
{
    extern __shared__ char smem[];
    float* sAcc = reinterpret_cast<float*>(smem + QK_NSTG * QK_STAGE);
    const int tid = threadIdx.x, wid = tid >> 5, lane = tid & 31;
    const int b = blockIdx.z, h = blockIdx.y;
    const int n0 = blockIdx.x * QK_SLAB;

    const __half* srcs[2] = {
        dwh + ((size_t)b * C3 + h * CH) * NPTS,
        dwh + ((size_t)b * C3 + C + h * CH) * NPTS
    };
    const uint32_t sbase = smem_u32(smem);

    for (int i = tid; i < 48 * 49; i += 256) sAcc[i] = 0.f;

    int la[6], lr[6], lc[6];
    #pragma unroll
    for (int q = 0; q < 6; q++) {
        int idx = tid + q * 256;
        la[q] = idx / 768;
        int rem = idx % 768;
        lr[q] = rem / 16;
        lc[q] = (rem % 16) * 8;
    }

    const int NCH = QK_SLAB / QKC;   // 16
    auto prefetch = [&](int ch) {
        uint32_t st = (uint32_t)(ch % QK_NSTG) * QK_STAGE;
        int nb = n0 + ch * QKC;
        #pragma unroll
        for (int q = 0; q < 6; q++) {
            uint32_t dst = sbase + st + la[q] * QK_ARR + (lr[q] * QKP + lc[q]) * 2;
            CP_CG16(dst, srcs[la[q]] + (size_t)lr[q] * NPTS + nb + lc[q]);
        }
        CP_COMMIT();
    };

    prefetch(0);
    prefetch(1);
    prefetch(2);

    float acc[3][6][4] = {};
    const int k0 = wid * 16;

    for (int ch = 0; ch < NCH; ch++) {
        if (ch < NCH - 2)      asm volatile("cp.async.wait_group 2;");
        else if (ch < NCH - 1) asm volatile("cp.async.wait_group 1;");
        else                   asm volatile("cp.async.wait_group 0;");
        __syncthreads();
        if (ch + 3 < NCH) prefetch(ch + 3);

        const uint32_t st = sbase + (uint32_t)(ch % QK_NSTG) * QK_STAGE;
        uint32_t Af[3][4], Bf[6][2];
        #pragma unroll
        for (int i = 0; i < 3; i++) {
            uint32_t off = ((i * 16 + (lane & 15)) * QKP + k0 + (lane >> 4) * 8) * 2;
            ldsm4(Af[i], st + off);
        }
        #pragma unroll
        for (int jj = 0; jj < 3; jj++) {
            uint32_t r[4];
            uint32_t off = ((jj * 16 + (lane & 7) + ((lane >> 4) << 3)) * QKP +
                            k0 + ((lane >> 3) & 1) * 8) * 2;
            ldsm4(r, st + QK_ARR + off);
            Bf[2 * jj][0] = r[0]; Bf[2 * jj][1] = r[1];
            Bf[2 * jj + 1][0] = r[2]; Bf[2 * jj + 1][1] = r[3];
        }
        #pragma unroll
        for (int i = 0; i < 3; i++)
            #pragma unroll
            for (int j = 0; j < 6; j++)
                mma_f16(acc[i][j], Af[i], Bf[j]);
    }

    __syncthreads();
    #pragma unroll
    for (int i = 0; i < 3; i++) {
        int m = i * 16 + (lane >> 2);
        #pragma unroll
        for (int j = 0; j < 6; j++) {
            int n = j * 8 + (lane & 3) * 2;
            atomicAdd(&sAcc[m * 49 + n],           acc[i][j][0]);
            atomicAdd(&sAcc[m * 49 + n + 1],       acc[i][j][1]);
            atomicAdd(&sAcc[(m + 8) * 49 + n],     acc[i][j][2]);
            atomicAdd(&sAcc[(m + 8) * 49 + n + 1], acc[i][j][3]);
        }
    }
    __syncthreads();
    float* dst = attn + (size_t)(b * HEADS + h) * CH * CH;
    for (int i = tid; i < CH * CH; i += 256)
        atomicAdd(&dst[i], sAcc[(i / CH) * 49 + (i % CH)]);
}

// ---------------- fused softmax + proj∘attn weight build (8 blocks, 192 thr) -------
__global__ __launch_bounds__(192) void smfuse(
    const float* __restrict__ attn, const float* __restrict__ ssq,
    const float* __restrict__ temp, const float* __restrict__ proj_w,
    __half* __restrict__ w2)
{
    int bh = blockIdx.x;
    int h = bh % HEADS, b = bh / HEADS;
    __shared__ float At[CH][CH];
    const float* am = attn + (size_t)bh * CH * CH;
    const float t = temp[h];

    {
        int c = threadIdx.x >> 2, qq = threadIdx.x & 3;
        float iq = 1.f / fmaxf(sqrtf(ssq[b * 2 * C + h * CH + c]), EPS);
        float xv[12];
        float mx = -1e30f;
        #pragma unroll
        for (int u = 0; u < 12; u++) {
            int e = qq * 12 + u;
            float ik = 1.f / fmaxf(sqrtf(ssq[b * 2 * C + C + h * CH + e]), EPS);
            xv[u] = am[c * CH + e] * iq * ik * t;
            mx = fmaxf(mx, xv[u]);
        }
        mx = fmaxf(mx, __shfl_xor_sync(~0u, mx, 1));
        mx = fmaxf(mx, __shfl_xor_sync(~0u, mx, 2));
        float sm = 0.f;
        #pragma unroll
        for (int u = 0; u < 12; u++) { xv[u] = expf(xv[u] - mx); sm += xv[u]; }
        sm += __shfl_xor_sync(~0u, sm, 1);
        sm += __shfl_xor_sync(~0u, sm, 2);
        float r = 1.f / sm;
        #pragma unroll
        for (int u = 0; u < 12; u++) At[c][qq * 12 + u] = xv[u] * r;
    }
    __syncthreads();

    int o = threadIdx.x;
    float pr[CH];
    #pragma unroll
    for (int c = 0; c < CH; c++) pr[c] = proj_w[(size_t)o * C + h * CH + c];

    __half* dst = w2 + (size_t)b * C * C + (size_t)o * C + h * CH;
    #pragma unroll 4
    for (int e = 0; e < CH; e++) {
        float acc = 0.f;
        #pragma unroll
        for (int c = 0; c < CH; c++) acc += pr[c] * At[c][e];
        dst[e] = __float2half_rn(acc);
    }
}

// ---------------- launch ----------------
extern "C" void kernel_launch(void* const* d_in, const int* in_sizes, int n_in,
                              void* d_out, int out_size)
{
    const float* x      = (const float*)d_in[0];
    const float* qkv_w  = (const float*)d_in[1];
    const float* qkv_b  = (const float*)d_in[2];
    const float* dw_w   = (const float*)d_in[3];
    const float* dw_b   = (const float*)d_in[4];
    const float* proj_w = (const float*)d_in[5];
    const float* proj_b = (const float*)d_in[6];
    const float* temp   = (const float*)d_in[7];
    float* out = (float*)d_out;

    float *ssqp, *atp;
    __half *xhp, *qkvhp, *dwhp, *whp, *w2p;
    cudaGetSymbolAddress((void**)&xhp,   g_xh);
    cudaGetSymbolAddress((void**)&qkvhp, g_qkvh);
    cudaGetSymbolAddress((void**)&dwhp,  g_dwh);
    cudaGetSymbolAddress((void**)&ssqp,  g_ssq);
    cudaGetSymbolAddress((void**)&atp,   g_at);
    cudaGetSymbolAddress((void**)&whp,   g_wh);
    cudaGetSymbolAddress((void**)&w2p,   g_w2h);

    cudaFuncSetAttribute(qk_mma, cudaFuncAttributeMaxDynamicSharedMemorySize, QK_SMEM);
    cudaFuncSetAttribute(gemm_mma<1>, cudaFuncAttributeMaxDynamicSharedMemorySize, GM_SMEM);
    cudaFuncSetAttribute(gemm_mma<0>, cudaFuncAttributeMaxDynamicSharedMemorySize, GM_SMEM);

    const size_t SETUP_N = XG + (size_t)C3 * C + B * HEADS * CH * CH;
    // 1) unified setup (x->fp16, W->fp16, zero attn)
    setupk<<<(int)((SETUP_N + 255) / 256), 256>>>(x, xhp, qkv_w, whp, atp);
    // 2) qkv 1x1 conv
    gemm_mma<1><<<dim3(C3 / BMg, NPTS / BNg, B), 256, GM_SMEM>>>(
        xhp, (size_t)C * NPTS, whp, 0, qkv_b, qkvhp, (size_t)C3 * NPTS);
    // 3) depthwise 3x3x3
    dwconv3<<<B * C3, 256>>>(qkvhp, dw_w, dw_b, dwhp, ssqp);
    // 4) q @ k^T (4-stage, NSPL=16, single wave) <- PROFILED
    qk_mma<<<dim3(QK_NSPL, HEADS, B), 256, QK_SMEM>>>(dwhp, atp);
    // 5) fused softmax + proj∘attn weights
    smfuse<<<B * HEADS, 192>>>(atp, ssqp, temp, proj_w, w2p);
    // 6) fused (proj∘attn) @ v
    gemm_mma<0><<<dim3(C / BMg, NPTS / BNg, B), 256, GM_SMEM>>>(
        dwhp + (size_t)2 * C * NPTS, (size_t)C3 * NPTS,
        w2p, (size_t)C * C, proj_b, out, (size_t)C * NPTS);
}